// round 6
// baseline (speedup 1.0000x reference)
#include <cuda_runtime.h>
#include <math.h>

#define T_FFT 512
#define LOG2M 14
#define MF    16384      // complex FFT length (real length N = 32768)
#define HALF  8192       // MF/2
#define LSEQ  16384
#define QB    4096       // MF/4 butterflies per radix-4 stage
#define PADI(i) ((i) + ((i) >> 4))

// ---------------- device scratch ----------------
__device__ float  g_W[128 * 64];
__device__ float  g_V[128 * 64];
__device__ float  g_K[LSEQ];
__device__ float2 g_H[MF + 1];
__device__ float2 g_twC[128];   // e^{-2pi i h/128}
__device__ float2 g_twF[128];   // e^{-2pi i l/16384}
__device__ float2 g_twCN[128];  // e^{-2pi i h/256}
__device__ float2 g_twFN[128];  // e^{-2pi i l/32768}

__device__ __forceinline__ float2 cmul(float2 a, float2 b) {
    return make_float2(a.x * b.x - a.y * b.y, a.x * b.y + a.y * b.x);
}
__device__ __forceinline__ float2 cconj(float2 a) { return make_float2(a.x, -a.y); }
__device__ __forceinline__ float2 cadd(float2 a, float2 b) { return make_float2(a.x + b.x, a.y + b.y); }
__device__ __forceinline__ float2 csub(float2 a, float2 b) { return make_float2(a.x - b.x, a.y - b.y); }
__device__ __forceinline__ float2 cmulni(float2 a) { return make_float2(a.y, -a.x); }  // -i*a
__device__ __forceinline__ float2 cmuli(float2 a)  { return make_float2(-a.y, a.x); }  // +i*a

__device__ __forceinline__ float2 twid(const float2* tC, const float2* tF, int x) {
    return cmul(tC[x >> 7], tF[x & 127]);   // e^{-2pi i x / 16384}, x < 16384
}

// digit-reverse base-4 of a 14-bit index
__device__ __forceinline__ int rev4_14(int k) {
    unsigned br = __brev((unsigned)k) >> 18;
    return (int)(((br & 0x2AAAu) >> 1) | ((br & 0x1555u) << 1));
}

// 16-point tail twiddles: w^j, w^2j, w^3j with w = e^{-2pi i/16}
__constant__ float2 c_w16a[4] = {
    {1.0f, 0.0f}, {0.92387953251f, -0.38268343236f},
    {0.70710678119f, -0.70710678119f}, {0.38268343236f, -0.92387953251f}};
__constant__ float2 c_w16b[4] = {
    {1.0f, 0.0f}, {0.70710678119f, -0.70710678119f},
    {0.0f, -1.0f}, {-0.70710678119f, -0.70710678119f}};
__constant__ float2 c_w16c[4] = {
    {1.0f, 0.0f}, {0.38268343236f, -0.92387953251f},
    {-0.70710678119f, -0.70710678119f}, {-0.92387953251f, 0.38268343236f}};

// ---------- forward FFT: fused global-load first stage (upper half zero) ----
__device__ void fft_fwd(float2* s, const float2* tC, const float2* tF,
                        const float2* __restrict__ gin) {
    const int tid = threadIdx.x;
    #pragma unroll
    for (int it = 0; it < QB / T_FFT; ++it) {
        int q = tid + it * T_FFT;           // 0..4095
        float2 a = gin[q];
        float2 b = gin[q + 4096];
        float2 w1 = twid(tC, tF, q);
        float2 w2 = twid(tC, tF, 2 * q);
        float2 w3 = twid(tC, tF, 3 * q);
        s[PADI(q)]         = cadd(a, b);
        s[PADI(q + 4096)]  = cmul(cadd(a, cmulni(b)), w1);
        s[PADI(q + 8192)]  = cmul(csub(a, b), w2);
        s[PADI(q + 12288)] = cmul(cadd(a, cmuli(b)), w3);
    }
    __syncthreads();
    #pragma unroll
    for (int st = 0; st < 4; ++st) {
        const int lg = 10 - 2 * st;
        const int H = 1 << lg;
        #pragma unroll
        for (int it = 0; it < QB / T_FFT; ++it) {
            int q = tid + it * T_FFT;
            int j = q & (H - 1);
            int i0 = ((q >> lg) << (lg + 2)) + j;
            float2 a = s[PADI(i0)], b = s[PADI(i0 + H)];
            float2 c = s[PADI(i0 + 2 * H)], d = s[PADI(i0 + 3 * H)];
            float2 y0 = cadd(a, c), y1 = csub(a, c);
            float2 y2 = cadd(b, d), y3 = csub(b, d);
            int x = j << (12 - lg);
            float2 w1 = twid(tC, tF, x);
            float2 w2 = twid(tC, tF, 2 * x);
            float2 w3 = twid(tC, tF, 3 * x);
            float2 m3 = cmulni(y3);
            s[PADI(i0)]         = cadd(y0, y2);
            s[PADI(i0 + H)]     = cmul(cadd(y1, m3), w1);
            s[PADI(i0 + 2 * H)] = cmul(csub(y0, y2), w2);
            s[PADI(i0 + 3 * H)] = cmul(csub(y1, m3), w3);
        }
        __syncthreads();
    }
    #pragma unroll
    for (int it = 0; it < (MF / 16) / T_FFT; ++it) {
        int m = tid + it * T_FFT;
        int base = 16 * m;
        float2 v[16];
        #pragma unroll
        for (int e = 0; e < 16; ++e) v[e] = s[PADI(base + e)];
        #pragma unroll
        for (int j = 0; j < 4; ++j) {
            float2 a = v[j], b = v[j + 4], c = v[j + 8], d = v[j + 12];
            float2 y0 = cadd(a, c), y1 = csub(a, c);
            float2 y2 = cadd(b, d), y3 = csub(b, d);
            float2 m3 = cmulni(y3);
            v[j]      = cadd(y0, y2);
            v[j + 4]  = cmul(cadd(y1, m3), c_w16a[j]);
            v[j + 8]  = cmul(csub(y0, y2), c_w16b[j]);
            v[j + 12] = cmul(csub(y1, m3), c_w16c[j]);
        }
        #pragma unroll
        for (int g = 0; g < 4; ++g) {
            float2 a = v[4 * g], b = v[4 * g + 1], c = v[4 * g + 2], d = v[4 * g + 3];
            float2 y0 = cadd(a, c), y1 = csub(a, c);
            float2 y2 = cadd(b, d), y3 = csub(b, d);
            float2 m3 = cmulni(y3);
            v[4 * g]     = cadd(y0, y2);
            v[4 * g + 1] = cadd(y1, m3);
            v[4 * g + 2] = csub(y0, y2);
            v[4 * g + 3] = csub(y1, m3);
        }
        #pragma unroll
        for (int e = 0; e < 16; ++e) s[PADI(base + e)] = v[e];
    }
    __syncthreads();
}

// ---------- inverse FFT: fused last stage writes z + D*u directly to gmem ---
__device__ void fft_inv(float2* s, const float2* tC, const float2* tF,
                        float2* __restrict__ gout, const float2* __restrict__ gu,
                        float Dv) {
    const int tid = threadIdx.x;
    #pragma unroll
    for (int it = 0; it < (MF / 16) / T_FFT; ++it) {
        int m = tid + it * T_FFT;
        int base = 16 * m;
        float2 v[16];
        #pragma unroll
        for (int e = 0; e < 16; ++e) v[e] = s[PADI(base + e)];
        #pragma unroll
        for (int g = 0; g < 4; ++g) {
            float2 b0 = v[4 * g], b1 = v[4 * g + 1], b2 = v[4 * g + 2], b3 = v[4 * g + 3];
            float2 y0 = cadd(b0, b2), y1 = csub(b0, b2);
            float2 y2 = cadd(b1, b3), y3 = cmuli(csub(b1, b3));
            v[4 * g]     = cadd(y0, y2);
            v[4 * g + 1] = cadd(y1, y3);
            v[4 * g + 2] = csub(y0, y2);
            v[4 * g + 3] = csub(y1, y3);
        }
        #pragma unroll
        for (int j = 0; j < 4; ++j) {
            float2 b0 = v[j];
            float2 t1 = cmul(v[j + 4],  cconj(c_w16a[j]));
            float2 t2 = cmul(v[j + 8],  cconj(c_w16b[j]));
            float2 t3 = cmul(v[j + 12], cconj(c_w16c[j]));
            float2 y0 = cadd(b0, t2), y1 = csub(b0, t2);
            float2 y2 = cadd(t1, t3), y3 = cmuli(csub(t1, t3));
            v[j]      = cadd(y0, y2);
            v[j + 4]  = cadd(y1, y3);
            v[j + 8]  = csub(y0, y2);
            v[j + 12] = csub(y1, y3);
        }
        #pragma unroll
        for (int e = 0; e < 16; ++e) s[PADI(base + e)] = v[e];
    }
    __syncthreads();
    #pragma unroll
    for (int st = 0; st < 4; ++st) {
        const int lg = 4 + 2 * st;
        const int H = 1 << lg;
        #pragma unroll
        for (int it = 0; it < QB / T_FFT; ++it) {
            int q = tid + it * T_FFT;
            int j = q & (H - 1);
            int i0 = ((q >> lg) << (lg + 2)) + j;
            int x = j << (12 - lg);
            float2 w1 = cconj(twid(tC, tF, x));
            float2 w2 = cconj(twid(tC, tF, 2 * x));
            float2 w3 = cconj(twid(tC, tF, 3 * x));
            float2 b0 = s[PADI(i0)];
            float2 t1 = cmul(s[PADI(i0 + H)], w1);
            float2 t2 = cmul(s[PADI(i0 + 2 * H)], w2);
            float2 t3 = cmul(s[PADI(i0 + 3 * H)], w3);
            float2 y0 = cadd(b0, t2), y1 = csub(b0, t2);
            float2 y2 = cadd(t1, t3), y3 = cmuli(csub(t1, t3));
            s[PADI(i0)]         = cadd(y0, y2);
            s[PADI(i0 + H)]     = cadd(y1, y3);
            s[PADI(i0 + 2 * H)] = csub(y0, y2);
            s[PADI(i0 + 3 * H)] = csub(y1, y3);
        }
        __syncthreads();
    }
    #pragma unroll
    for (int it = 0; it < QB / T_FFT; ++it) {
        int q = tid + it * T_FFT;
        float2 w1 = cconj(twid(tC, tF, q));
        float2 w2 = cconj(twid(tC, tF, 2 * q));
        float2 w3 = cconj(twid(tC, tF, 3 * q));
        float2 b0 = s[PADI(q)];
        float2 t1 = cmul(s[PADI(q + 4096)], w1);
        float2 t2 = cmul(s[PADI(q + 8192)], w2);
        float2 t3 = cmul(s[PADI(q + 12288)], w3);
        float2 y0 = cadd(b0, t2), y1 = csub(b0, t2);
        float2 y2 = cadd(t1, t3), y3 = cmuli(csub(t1, t3));
        float2 z0 = cadd(y0, y2);
        float2 z1 = cadd(y1, y3);
        float2 u0 = gu[q], u1 = gu[q + 4096];
        gout[q]        = make_float2(z0.x + Dv * u0.x, z0.y + Dv * u0.y);
        gout[q + 4096] = make_float2(z1.x + Dv * u1.x, z1.y + Dv * u1.y);
    }
}

// ---------- fp64 64x64 matmul (squaring): Dst = S*S. 128 threads, bar 1 -----
__device__ void mmD(const double* S, double* Dst, int tid) {
    const int ty = tid >> 3;     // 0..15 -> rows 4*ty..4*ty+3
    const int tx = tid & 7;      // 0..7  -> cols 8*tx..8*tx+7
    double acc[4][8];
    #pragma unroll
    for (int i = 0; i < 4; ++i)
        #pragma unroll
        for (int j = 0; j < 8; ++j) acc[i][j] = 0.0;
    for (int k = 0; k < 64; ++k) {
        double b[8];
        #pragma unroll
        for (int j = 0; j < 8; ++j) b[j] = S[k * 64 + 8 * tx + j];
        double a[4];
        #pragma unroll
        for (int i = 0; i < 4; ++i) a[i] = S[(4 * ty + i) * 64 + k];
        #pragma unroll
        for (int i = 0; i < 4; ++i)
            #pragma unroll
            for (int j = 0; j < 8; ++j) acc[i][j] += a[i] * b[j];
    }
    #pragma unroll
    for (int i = 0; i < 4; ++i)
        #pragma unroll
        for (int j = 0; j < 8; ++j) Dst[(4 * ty + i) * 64 + 8 * tx + j] = acc[i][j];
    asm volatile("bar.sync 1, 128;" ::: "memory");
}

// ---------------- kernel 1: twiddles + fp64 discretize/powers + chains ------
// smem layout (bytes):
//   [0, 67584)        augD double[64*132]  -> reused after GJ as WF float[8192] @0, VF float[8192] @32768
//   [67584, 100352)   SD0 double[4096]
//   [100352, 133120)  SD1 double[4096]
//   [133120, 149504)  AbF float[4096]   (row-major Ab, fp32)
//   [149504, 165888)  MT  float[4096]   (M128^T, later M512^T, fp32)
//   [165888, 166400)  fcolD double[64]
//   [166400, 166656)  BbF float[64]
//   [166656, 166664)  sInvD double
#define SMEM_PREP_BYTES 166912

__global__ __launch_bounds__(256) void k_prep(const float* __restrict__ A,
                                              const float* __restrict__ B,
                                              const float* __restrict__ C,
                                              const float* __restrict__ logstep) {
    extern __shared__ char smc[];
    double* augD  = reinterpret_cast<double*>(smc);
    float*  WF    = reinterpret_cast<float*>(smc);
    float*  VF    = reinterpret_cast<float*>(smc + 32768);
    double* SD0   = reinterpret_cast<double*>(smc + 67584);
    double* SD1   = reinterpret_cast<double*>(smc + 100352);
    float*  AbF   = reinterpret_cast<float*>(smc + 133120);
    float*  MT    = reinterpret_cast<float*>(smc + 149504);
    double* fcolD = reinterpret_cast<double*>(smc + 165888);
    float*  BbF   = reinterpret_cast<float*>(smc + 166400);
    double* sInvD = reinterpret_cast<double*>(smc + 166656);
    __shared__ double s_hs, s_st;
    const int tid = threadIdx.x;

    // twiddle tables (fp64) -> global
    if (tid < 128) {
        const double PI = 3.14159265358979323846;
        double sv, cv, ang;
        ang = -2.0 * PI * (double)tid / 128.0;    sincos(ang, &sv, &cv);
        g_twC[tid] = make_float2((float)cv, (float)sv);
        ang = -2.0 * PI * (double)tid / 16384.0;  sincos(ang, &sv, &cv);
        g_twF[tid] = make_float2((float)cv, (float)sv);
        ang = -2.0 * PI * (double)tid / 256.0;    sincos(ang, &sv, &cv);
        g_twCN[tid] = make_float2((float)cv, (float)sv);
        ang = -2.0 * PI * (double)tid / 32768.0;  sincos(ang, &sv, &cv);
        g_twFN[tid] = make_float2((float)cv, (float)sv);
    }
    if (tid == 0) {
        // match the reference's fp32 quantization of step, then go fp64
        float stf = (float)exp((double)logstep[0]);
        s_st = (double)stf;
        s_hs = 0.5 * (double)stf;
    }
    __syncthreads();
    const double hs = s_hs;
    const double st = s_st;

    // augD = [I - hs*A | I + hs*A | st*B], fp64
    for (int idx = tid; idx < 64 * 129; idx += 256) {
        int r = idx / 129, c = idx % 129;
        double v;
        if (c < 64)       v = (r == c ? 1.0 : 0.0) - hs * (double)A[r * 64 + c];
        else if (c < 128) v = (r == (c - 64) ? 1.0 : 0.0) + hs * (double)A[r * 64 + (c - 64)];
        else              v = st * (double)B[r];
        augD[r * 132 + c] = v;
    }
    __syncthreads();

    // fp64 Gauss-Jordan (no pivoting; I - hs*A is strongly diag-dominant)
    const int gr  = tid >> 2;
    const int gc0 = tid & 3;
    for (int col = 0; col < 64; ++col) {
        if (tid == 0) sInvD[0] = 1.0 / augD[col * 132 + col];
        __syncthreads();
        double inv = sInvD[0];
        for (int c = tid; c < 129; c += 256) augD[col * 132 + c] *= inv;
        if (tid < 64) fcolD[tid] = (tid == col) ? 0.0 : augD[tid * 132 + col];
        __syncthreads();
        double f = fcolD[gr];
        for (int c = gc0; c < 129; c += 4)
            augD[gr * 132 + c] -= f * augD[col * 132 + c];
        __syncthreads();
    }

    // extract Ab (fp64 -> SD0, fp32 -> AbF) and Bb (fp32 -> BbF) BEFORE augD reuse
    for (int idx = tid; idx < 4096; idx += 256) {
        int r = idx >> 6, c = idx & 63;
        double v = augD[r * 132 + 64 + c];
        SD0[idx] = v;
        AbF[idx] = (float)v;
    }
    if (tid < 64) BbF[tid] = (float)augD[tid * 132 + 128];
    __syncthreads();

    // augD now dead: initialize WF row 0 = C, VF row 0 = Bb
    if (tid < 64) { WF[tid] = C[tid]; VF[tid] = BbF[tid]; }
    __syncthreads();

    // ---- phase B: fp64 squarings (warps 0-3) || fp32 W chain (warps 4-7) ----
    double* Sa = SD0;
    double* Sb = SD1;
    if (tid < 128) {
        for (int t = 0; t < 7; ++t) {           // Sa ends as Ab^128
            mmD(Sa, Sb, tid);
            double* tmp = Sa; Sa = Sb; Sb = tmp;
        }
        // MT = fp32 transpose of Ab^128
        for (int idx = tid; idx < 4096; idx += 128)
            MT[idx] = (float)Sa[(idx & 63) * 64 + (idx >> 6)];
    } else {
        const int tid2 = tid - 128;
        for (int stp = 1; stp < 128; ++stp) {
            float acc0 = 0.f, acc1 = 0.f, acc2 = 0.f, acc3 = 0.f;
            if (tid2 < 64) {
                const float* wrow = WF + (stp - 1) * 64;
                #pragma unroll 16
                for (int r = 0; r < 64; r += 4) {
                    acc0 += wrow[r + 0] * AbF[(r + 0) * 64 + tid2];
                    acc1 += wrow[r + 1] * AbF[(r + 1) * 64 + tid2];
                    acc2 += wrow[r + 2] * AbF[(r + 2) * 64 + tid2];
                    acc3 += wrow[r + 3] * AbF[(r + 3) * 64 + tid2];
                }
            }
            asm volatile("bar.sync 2, 128;" ::: "memory");
            if (tid2 < 64) WF[stp * 64 + tid2] = (acc0 + acc1) + (acc2 + acc3);
            asm volatile("bar.sync 2, 128;" ::: "memory");
        }
    }
    __syncthreads();
    // NOTE: Sa/Sb pointers in warps 4-7 are stale; recompute canonical: after 7
    // swaps starting (SD0,SD1): odd count -> Ab^128 lives in SD1.
    double* S128 = SD1;
    double* Sfree = SD0;

    // V seeds: VF rows 1..3 via MT = (Ab^128)^T
    for (int sd = 1; sd <= 3; ++sd) {
        float acc = 0.f;
        if (tid < 64) {
            const float* vprev = VF + (sd - 1) * 64;
            float a0 = 0.f, a1 = 0.f, a2 = 0.f, a3 = 0.f;
            #pragma unroll 16
            for (int c = 0; c < 64; c += 4) {
                a0 += MT[(c + 0) * 64 + tid] * vprev[c + 0];
                a1 += MT[(c + 1) * 64 + tid] * vprev[c + 1];
                a2 += MT[(c + 2) * 64 + tid] * vprev[c + 2];
                a3 += MT[(c + 3) * 64 + tid] * vprev[c + 3];
            }
            acc = (a0 + a1) + (a2 + a3);
        }
        __syncthreads();
        if (tid < 64) VF[sd * 64 + tid] = acc;
        __syncthreads();
    }

    // squarings 8,9: Ab^256, Ab^512 (warps 0-3), then MT = (Ab^512)^T fp32
    if (tid < 128) {
        mmD(S128, Sfree, tid);        // Sfree = Ab^256
        mmD(Sfree, S128, tid);        // S128  = Ab^512
        for (int idx = tid; idx < 4096; idx += 128)
            MT[idx] = (float)S128[(idx & 63) * 64 + (idx >> 6)];
    }
    __syncthreads();

    // V chains: 4 chains stepped by Ab^512; V[ch + 4*sp] = M512 * V[ch + 4*(sp-1)]
    {
        const int ch = tid >> 6, r = tid & 63;
        for (int sp = 1; sp <= 31; ++sp) {
            const float* vprev = VF + (ch + 4 * (sp - 1)) * 64;
            float a0 = 0.f, a1 = 0.f, a2 = 0.f, a3 = 0.f;
            #pragma unroll 16
            for (int c = 0; c < 64; c += 4) {
                a0 += MT[(c + 0) * 64 + r] * vprev[c + 0];
                a1 += MT[(c + 1) * 64 + r] * vprev[c + 1];
                a2 += MT[(c + 2) * 64 + r] * vprev[c + 2];
                a3 += MT[(c + 3) * 64 + r] * vprev[c + 3];
            }
            float acc = (a0 + a1) + (a2 + a3);
            __syncthreads();
            VF[(ch + 4 * sp) * 64 + r] = acc;
            __syncthreads();
        }
    }

    // write W, V to global
    for (int idx = tid; idx < 8192; idx += 256) {
        g_W[idx] = WF[idx];
        g_V[idx] = VF[idx];
    }
}

// ---------------- kernel 2: K[128 i + j] = W[j] . V[i] ----------------------
__global__ __launch_bounds__(128) void k_K() {
    int il = blockIdx.x * 128 + threadIdx.x;
    int j = il & 127, i = il >> 7;
    float acc = 0.f;
    #pragma unroll 8
    for (int r = 0; r < 64; ++r) acc += g_W[j * 64 + r] * g_V[i * 64 + r];
    g_K[il] = acc;
}

// ---------------- kernel 3: H = rfft(K, 32768) / MF -------------------------
__global__ __launch_bounds__(T_FFT) void k_kfft() {
    extern __shared__ float2 sh2[];
    float2* s   = sh2;
    float2* tC  = s + 17408;
    float2* tF  = tC + 128;
    float2* tCN = tF + 128;
    float2* tFN = tCN + 128;
    const int tid = threadIdx.x;
    if (tid < 128) {
        tC[tid] = g_twC[tid]; tF[tid] = g_twF[tid];
        tCN[tid] = g_twCN[tid]; tFN[tid] = g_twFN[tid];
    }
    __syncthreads();
    fft_fwd(s, tC, tF, reinterpret_cast<const float2*>(g_K));

    const float sc = 1.0f / (float)MF;
    if (tid == 0) {
        float2 Z0 = s[PADI(0)];
        g_H[0]  = make_float2((Z0.x + Z0.y) * sc, 0.f);
        g_H[MF] = make_float2((Z0.x - Z0.y) * sc, 0.f);
    }
    for (int k = tid + 1; k <= HALF; k += T_FFT) {
        int rk = PADI(rev4_14(k));
        int rm = PADI(rev4_14(MF - k));
        float2 a  = s[rk];
        float2 bb = cconj(s[rm]);
        float2 E  = make_float2(0.5f * (a.x + bb.x), 0.5f * (a.y + bb.y));
        float2 Od = make_float2(0.5f * (a.x - bb.x), 0.5f * (a.y - bb.y));
        float2 wN = cmul(tCN[k >> 7], tFN[k & 127]);
        float2 g  = make_float2(wN.y, -wN.x);
        float2 gOd = cmul(g, Od);
        g_H[k]      = make_float2((E.x + gOd.x) * sc, (E.y + gOd.y) * sc);
        g_H[MF - k] = make_float2((E.x - gOd.x) * sc, -(E.y - gOd.y) * sc);
    }
}

// ---------------- kernel 4: per-row FFT conv + D*u --------------------------
__global__ __launch_bounds__(T_FFT) void k_conv(const float* __restrict__ u,
                                                const float* __restrict__ Dp,
                                                float* __restrict__ out) {
    extern __shared__ float2 sh2[];
    float2* s   = sh2;
    float2* tC  = s + 17408;
    float2* tF  = tC + 128;
    float2* tCN = tF + 128;
    float2* tFN = tCN + 128;
    const int tid = threadIdx.x;
    const int b = blockIdx.x;
    if (tid < 128) {
        tC[tid] = g_twC[tid]; tF[tid] = g_twF[tid];
        tCN[tid] = g_twCN[tid]; tFN[tid] = g_twFN[tid];
    }
    __syncthreads();

    const float2* u2 = reinterpret_cast<const float2*>(u) + (size_t)b * HALF;
    fft_fwd(s, tC, tF, u2);

    if (tid == 0) {
        float2 Z0 = s[PADI(0)];
        float X0 = Z0.x + Z0.y;
        float XM = Z0.x - Z0.y;
        float Y0 = X0 * g_H[0].x;
        float YM = XM * g_H[MF].x;
        s[PADI(0)] = make_float2(0.5f * (Y0 + YM), 0.5f * (Y0 - YM));
    }
    for (int k = tid + 1; k <= HALF; k += T_FFT) {
        int rk = PADI(rev4_14(k));
        int rm = PADI(rev4_14(MF - k));
        float2 a  = s[rk];
        float2 bb = cconj(s[rm]);
        float2 E  = make_float2(0.5f * (a.x + bb.x), 0.5f * (a.y + bb.y));
        float2 Od = make_float2(0.5f * (a.x - bb.x), 0.5f * (a.y - bb.y));
        float2 wN = cmul(tCN[k >> 7], tFN[k & 127]);
        float2 g  = make_float2(wN.y, -wN.x);
        float2 gOd = cmul(g, Od);
        float2 Xk = make_float2(E.x + gOd.x, E.y + gOd.y);
        float2 Xm = make_float2(E.x - gOd.x, -(E.y - gOd.y));
        float2 Yk = cmul(Xk, g_H[k]);
        float2 Ym = cmul(Xm, g_H[MF - k]);
        float2 cYm = cconj(Ym);
        float2 Ep  = make_float2(0.5f * (Yk.x + cYm.x), 0.5f * (Yk.y + cYm.y));
        float2 Dd  = make_float2(0.5f * (Yk.x - cYm.x), 0.5f * (Yk.y - cYm.y));
        float2 t1 = cmul(cconj(g), Dd);
        float2 t2 = cmul(g, cconj(Dd));
        s[rk] = make_float2(Ep.x + t1.x, Ep.y + t1.y);
        s[rm] = make_float2(Ep.x - t2.x, -Ep.y - t2.y);
    }
    __syncthreads();

    const float Dv = Dp[0];
    float2* o2 = reinterpret_cast<float2*>(out) + (size_t)b * HALF;
    fft_inv(s, tC, tF, o2, u2, Dv);
}

// ---------------- launch ----------------------------------------------------
extern "C" void kernel_launch(void* const* d_in, const int* in_sizes, int n_in,
                              void* d_out, int out_size) {
    const float* u  = (const float*)d_in[0];
    const float* A  = (const float*)d_in[1];
    const float* B  = (const float*)d_in[2];
    const float* C  = (const float*)d_in[3];
    const float* D  = (const float*)d_in[4];
    const float* ls = (const float*)d_in[5];
    float* out = (float*)d_out;

    const int smemFFT = (17408 + 4 * 128) * (int)sizeof(float2);   // 143360

    cudaFuncSetAttribute(k_prep, cudaFuncAttributeMaxDynamicSharedMemorySize, SMEM_PREP_BYTES);
    cudaFuncSetAttribute(k_kfft, cudaFuncAttributeMaxDynamicSharedMemorySize, smemFFT);
    cudaFuncSetAttribute(k_conv, cudaFuncAttributeMaxDynamicSharedMemorySize, smemFFT);

    k_prep<<<1, 256, SMEM_PREP_BYTES>>>(A, B, C, ls);
    k_K<<<128, 128>>>();
    k_kfft<<<1, T_FFT, smemFFT>>>();
    k_conv<<<512, T_FFT, smemFFT>>>(u, D, out);
}

// round 7
// speedup vs baseline: 2.6202x; 2.6202x over previous
#include <cuda_runtime.h>
#include <math.h>

#define T_FFT 512
#define LOG2M 14
#define MF    16384      // complex FFT length (real length N = 32768)
#define HALF  8192       // MF/2
#define LSEQ  16384
#define QB    4096       // MF/4 butterflies per radix-4 stage
#define PADI(i) ((i) + ((i) >> 4))

// ---------------- device scratch ----------------
__device__ float  g_W[128 * 64];
__device__ float  g_V[128 * 64];
__device__ float  g_K[LSEQ];
__device__ float2 g_H[MF + 1];
__device__ float2 g_twC[128];   // e^{-2pi i h/128}
__device__ float2 g_twF[128];   // e^{-2pi i l/16384}
__device__ float2 g_twCN[128];  // e^{-2pi i h/256}
__device__ float2 g_twFN[128];  // e^{-2pi i l/32768}

__device__ double g_SD0[4096];
__device__ double g_SD1[4096];
__device__ double g_RD[4096];
__device__ float  g_X0[4096];
__device__ float  g_AbF[4096];
__device__ float  g_M128T[4096];
__device__ float  g_M512T[4096];
__device__ float  g_BbF[64];
__device__ double g_stepD[2];   // hs, st

__device__ __forceinline__ float2 cmul(float2 a, float2 b) {
    return make_float2(a.x * b.x - a.y * b.y, a.x * b.y + a.y * b.x);
}
__device__ __forceinline__ float2 cconj(float2 a) { return make_float2(a.x, -a.y); }
__device__ __forceinline__ float2 cadd(float2 a, float2 b) { return make_float2(a.x + b.x, a.y + b.y); }
__device__ __forceinline__ float2 csub(float2 a, float2 b) { return make_float2(a.x - b.x, a.y - b.y); }
__device__ __forceinline__ float2 cmulni(float2 a) { return make_float2(a.y, -a.x); }  // -i*a
__device__ __forceinline__ float2 cmuli(float2 a)  { return make_float2(-a.y, a.x); }  // +i*a

__device__ __forceinline__ float2 twid(const float2* tC, const float2* tF, int x) {
    return cmul(tC[x >> 7], tF[x & 127]);   // e^{-2pi i x / 16384}, x < 16384
}

__device__ __forceinline__ int rev4_14(int k) {
    unsigned br = __brev((unsigned)k) >> 18;
    return (int)(((br & 0x2AAAu) >> 1) | ((br & 0x1555u) << 1));
}

__constant__ float2 c_w16a[4] = {
    {1.0f, 0.0f}, {0.92387953251f, -0.38268343236f},
    {0.70710678119f, -0.70710678119f}, {0.38268343236f, -0.92387953251f}};
__constant__ float2 c_w16b[4] = {
    {1.0f, 0.0f}, {0.70710678119f, -0.70710678119f},
    {0.0f, -1.0f}, {-0.70710678119f, -0.70710678119f}};
__constant__ float2 c_w16c[4] = {
    {1.0f, 0.0f}, {0.38268343236f, -0.92387953251f},
    {-0.70710678119f, -0.70710678119f}, {-0.92387953251f, 0.38268343236f}};

// ---------- forward FFT: fused global-load first stage (upper half zero) ----
__device__ void fft_fwd(float2* s, const float2* tC, const float2* tF,
                        const float2* __restrict__ gin) {
    const int tid = threadIdx.x;
    #pragma unroll
    for (int it = 0; it < QB / T_FFT; ++it) {
        int q = tid + it * T_FFT;
        float2 a = gin[q];
        float2 b = gin[q + 4096];
        float2 w1 = twid(tC, tF, q);
        float2 w2 = twid(tC, tF, 2 * q);
        float2 w3 = twid(tC, tF, 3 * q);
        s[PADI(q)]         = cadd(a, b);
        s[PADI(q + 4096)]  = cmul(cadd(a, cmulni(b)), w1);
        s[PADI(q + 8192)]  = cmul(csub(a, b), w2);
        s[PADI(q + 12288)] = cmul(cadd(a, cmuli(b)), w3);
    }
    __syncthreads();
    #pragma unroll
    for (int st = 0; st < 4; ++st) {
        const int lg = 10 - 2 * st;
        const int H = 1 << lg;
        #pragma unroll
        for (int it = 0; it < QB / T_FFT; ++it) {
            int q = tid + it * T_FFT;
            int j = q & (H - 1);
            int i0 = ((q >> lg) << (lg + 2)) + j;
            float2 a = s[PADI(i0)], b = s[PADI(i0 + H)];
            float2 c = s[PADI(i0 + 2 * H)], d = s[PADI(i0 + 3 * H)];
            float2 y0 = cadd(a, c), y1 = csub(a, c);
            float2 y2 = cadd(b, d), y3 = csub(b, d);
            int x = j << (12 - lg);
            float2 w1 = twid(tC, tF, x);
            float2 w2 = twid(tC, tF, 2 * x);
            float2 w3 = twid(tC, tF, 3 * x);
            float2 m3 = cmulni(y3);
            s[PADI(i0)]         = cadd(y0, y2);
            s[PADI(i0 + H)]     = cmul(cadd(y1, m3), w1);
            s[PADI(i0 + 2 * H)] = cmul(csub(y0, y2), w2);
            s[PADI(i0 + 3 * H)] = cmul(csub(y1, m3), w3);
        }
        __syncthreads();
    }
    #pragma unroll
    for (int it = 0; it < (MF / 16) / T_FFT; ++it) {
        int m = tid + it * T_FFT;
        int base = 16 * m;
        float2 v[16];
        #pragma unroll
        for (int e = 0; e < 16; ++e) v[e] = s[PADI(base + e)];
        #pragma unroll
        for (int j = 0; j < 4; ++j) {
            float2 a = v[j], b = v[j + 4], c = v[j + 8], d = v[j + 12];
            float2 y0 = cadd(a, c), y1 = csub(a, c);
            float2 y2 = cadd(b, d), y3 = csub(b, d);
            float2 m3 = cmulni(y3);
            v[j]      = cadd(y0, y2);
            v[j + 4]  = cmul(cadd(y1, m3), c_w16a[j]);
            v[j + 8]  = cmul(csub(y0, y2), c_w16b[j]);
            v[j + 12] = cmul(csub(y1, m3), c_w16c[j]);
        }
        #pragma unroll
        for (int g = 0; g < 4; ++g) {
            float2 a = v[4 * g], b = v[4 * g + 1], c = v[4 * g + 2], d = v[4 * g + 3];
            float2 y0 = cadd(a, c), y1 = csub(a, c);
            float2 y2 = cadd(b, d), y3 = csub(b, d);
            float2 m3 = cmulni(y3);
            v[4 * g]     = cadd(y0, y2);
            v[4 * g + 1] = cadd(y1, m3);
            v[4 * g + 2] = csub(y0, y2);
            v[4 * g + 3] = csub(y1, m3);
        }
        #pragma unroll
        for (int e = 0; e < 16; ++e) s[PADI(base + e)] = v[e];
    }
    __syncthreads();
}

// ---------- inverse FFT: fused last stage writes z + D*u directly to gmem ---
__device__ void fft_inv(float2* s, const float2* tC, const float2* tF,
                        float2* __restrict__ gout, const float2* __restrict__ gu,
                        float Dv) {
    const int tid = threadIdx.x;
    #pragma unroll
    for (int it = 0; it < (MF / 16) / T_FFT; ++it) {
        int m = tid + it * T_FFT;
        int base = 16 * m;
        float2 v[16];
        #pragma unroll
        for (int e = 0; e < 16; ++e) v[e] = s[PADI(base + e)];
        #pragma unroll
        for (int g = 0; g < 4; ++g) {
            float2 b0 = v[4 * g], b1 = v[4 * g + 1], b2 = v[4 * g + 2], b3 = v[4 * g + 3];
            float2 y0 = cadd(b0, b2), y1 = csub(b0, b2);
            float2 y2 = cadd(b1, b3), y3 = cmuli(csub(b1, b3));
            v[4 * g]     = cadd(y0, y2);
            v[4 * g + 1] = cadd(y1, y3);
            v[4 * g + 2] = csub(y0, y2);
            v[4 * g + 3] = csub(y1, y3);
        }
        #pragma unroll
        for (int j = 0; j < 4; ++j) {
            float2 b0 = v[j];
            float2 t1 = cmul(v[j + 4],  cconj(c_w16a[j]));
            float2 t2 = cmul(v[j + 8],  cconj(c_w16b[j]));
            float2 t3 = cmul(v[j + 12], cconj(c_w16c[j]));
            float2 y0 = cadd(b0, t2), y1 = csub(b0, t2);
            float2 y2 = cadd(t1, t3), y3 = cmuli(csub(t1, t3));
            v[j]      = cadd(y0, y2);
            v[j + 4]  = cadd(y1, y3);
            v[j + 8]  = csub(y0, y2);
            v[j + 12] = csub(y1, y3);
        }
        #pragma unroll
        for (int e = 0; e < 16; ++e) s[PADI(base + e)] = v[e];
    }
    __syncthreads();
    #pragma unroll
    for (int st = 0; st < 4; ++st) {
        const int lg = 4 + 2 * st;
        const int H = 1 << lg;
        #pragma unroll
        for (int it = 0; it < QB / T_FFT; ++it) {
            int q = tid + it * T_FFT;
            int j = q & (H - 1);
            int i0 = ((q >> lg) << (lg + 2)) + j;
            int x = j << (12 - lg);
            float2 w1 = cconj(twid(tC, tF, x));
            float2 w2 = cconj(twid(tC, tF, 2 * x));
            float2 w3 = cconj(twid(tC, tF, 3 * x));
            float2 b0 = s[PADI(i0)];
            float2 t1 = cmul(s[PADI(i0 + H)], w1);
            float2 t2 = cmul(s[PADI(i0 + 2 * H)], w2);
            float2 t3 = cmul(s[PADI(i0 + 3 * H)], w3);
            float2 y0 = cadd(b0, t2), y1 = csub(b0, t2);
            float2 y2 = cadd(t1, t3), y3 = cmuli(csub(t1, t3));
            s[PADI(i0)]         = cadd(y0, y2);
            s[PADI(i0 + H)]     = cadd(y1, y3);
            s[PADI(i0 + 2 * H)] = csub(y0, y2);
            s[PADI(i0 + 3 * H)] = csub(y1, y3);
        }
        __syncthreads();
    }
    #pragma unroll
    for (int it = 0; it < QB / T_FFT; ++it) {
        int q = tid + it * T_FFT;
        float2 w1 = cconj(twid(tC, tF, q));
        float2 w2 = cconj(twid(tC, tF, 2 * q));
        float2 w3 = cconj(twid(tC, tF, 3 * q));
        float2 b0 = s[PADI(q)];
        float2 t1 = cmul(s[PADI(q + 4096)], w1);
        float2 t2 = cmul(s[PADI(q + 8192)], w2);
        float2 t3 = cmul(s[PADI(q + 12288)], w3);
        float2 y0 = cadd(b0, t2), y1 = csub(b0, t2);
        float2 y2 = cadd(t1, t3), y3 = cmuli(csub(t1, t3));
        float2 z0 = cadd(y0, y2);
        float2 z1 = cadd(y1, y3);
        float2 u0 = gu[q], u1 = gu[q + 4096];
        gout[q]        = make_float2(z0.x + Dv * u0.x, z0.y + Dv * u0.y);
        gout[q + 4096] = make_float2(z1.x + Dv * u1.x, z1.y + Dv * u1.y);
    }
}

// ------- kernel 1: twiddles + steps + fp32 Gauss-Jordan inverse of M --------
__global__ __launch_bounds__(256) void k_disc(const float* __restrict__ A,
                                              const float* __restrict__ logstep) {
    __shared__ float aug[64 * 132];   // [M | I], padded width
    __shared__ float fcol[64];
    __shared__ float sinv;
    const int tid = threadIdx.x;

    if (tid < 128) {
        const double PI = 3.14159265358979323846;
        double sv, cv, ang;
        ang = -2.0 * PI * (double)tid / 128.0;    sincos(ang, &sv, &cv);
        g_twC[tid] = make_float2((float)cv, (float)sv);
        ang = -2.0 * PI * (double)tid / 16384.0;  sincos(ang, &sv, &cv);
        g_twF[tid] = make_float2((float)cv, (float)sv);
        ang = -2.0 * PI * (double)tid / 256.0;    sincos(ang, &sv, &cv);
        g_twCN[tid] = make_float2((float)cv, (float)sv);
        ang = -2.0 * PI * (double)tid / 32768.0;  sincos(ang, &sv, &cv);
        g_twFN[tid] = make_float2((float)cv, (float)sv);
    }
    if (tid == 0) {
        float stf = (float)exp((double)logstep[0]);  // match ref's fp32 step
        g_stepD[0] = 0.5 * (double)stf;
        g_stepD[1] = (double)stf;
    }
    __syncthreads();
    const float hs = (float)g_stepD[0];

    for (int idx = tid; idx < 64 * 128; idx += 256) {
        int r = idx >> 7, c = idx & 127;
        float v;
        if (c < 64) v = (r == c ? 1.f : 0.f) - hs * A[r * 64 + c];
        else        v = (r == (c - 64)) ? 1.f : 0.f;
        aug[r * 132 + c] = v;
    }
    __syncthreads();

    const int gr  = tid >> 2;
    const int gc0 = tid & 3;
    for (int col = 0; col < 64; ++col) {
        if (tid == 0) sinv = 1.0f / aug[col * 132 + col];
        __syncthreads();
        float inv = sinv;
        for (int c = tid; c < 128; c += 256) aug[col * 132 + c] *= inv;
        if (tid < 64) fcol[tid] = (tid == col) ? 0.f : aug[tid * 132 + col];
        __syncthreads();
        float f = fcol[gr];
        for (int c = gc0; c < 128; c += 4)
            aug[gr * 132 + c] -= f * aug[col * 132 + c];
        __syncthreads();
    }

    for (int idx = tid; idx < 4096; idx += 256) {
        int r = idx >> 6, c = idx & 63;
        g_X0[idx] = aug[r * 132 + 64 + c];
    }
}

// ------- kernel 2: R = I - M*X0  (fp64, 64 blocks x 64 threads) -------------
__global__ __launch_bounds__(64) void k_ref1(const float* __restrict__ A) {
    __shared__ float X0s[4096];
    __shared__ float Arow[64];
    const int r = blockIdx.x, c = threadIdx.x;
    for (int i = c; i < 4096; i += 64) X0s[i] = g_X0[i];
    Arow[c] = A[r * 64 + c];
    __syncthreads();
    const double hs = g_stepD[0];
    double a0 = 0.0, a1 = 0.0, a2 = 0.0, a3 = 0.0;
    #pragma unroll 4
    for (int k = 0; k < 64; k += 4) {
        double m0 = (r == k + 0 ? 1.0 : 0.0) - hs * (double)Arow[k + 0];
        double m1 = (r == k + 1 ? 1.0 : 0.0) - hs * (double)Arow[k + 1];
        double m2 = (r == k + 2 ? 1.0 : 0.0) - hs * (double)Arow[k + 2];
        double m3 = (r == k + 3 ? 1.0 : 0.0) - hs * (double)Arow[k + 3];
        a0 += m0 * (double)X0s[(k + 0) * 64 + c];
        a1 += m1 * (double)X0s[(k + 1) * 64 + c];
        a2 += m2 * (double)X0s[(k + 2) * 64 + c];
        a3 += m3 * (double)X0s[(k + 3) * 64 + c];
    }
    double acc = (a0 + a1) + (a2 + a3);
    g_RD[r * 64 + c] = (r == c ? 1.0 : 0.0) - acc;
}

// ------- kernel 3: X1 = X0 + X0*R; Ab = 2*X1 - I; Bb = st*X1*B --------------
__global__ __launch_bounds__(64) void k_ref2(const float* __restrict__ B) {
    __shared__ float X0s[4096];
    __shared__ double red[64];
    const int r = blockIdx.x, c = threadIdx.x;
    for (int i = c; i < 4096; i += 64) X0s[i] = g_X0[i];
    __syncthreads();
    double a0 = 0.0, a1 = 0.0, a2 = 0.0, a3 = 0.0;
    #pragma unroll 4
    for (int k = 0; k < 64; k += 4) {
        a0 += (double)X0s[r * 64 + k + 0] * g_RD[(k + 0) * 64 + c];
        a1 += (double)X0s[r * 64 + k + 1] * g_RD[(k + 1) * 64 + c];
        a2 += (double)X0s[r * 64 + k + 2] * g_RD[(k + 2) * 64 + c];
        a3 += (double)X0s[r * 64 + k + 3] * g_RD[(k + 3) * 64 + c];
    }
    double x1 = (double)X0s[r * 64 + c] + (a0 + a1) + (a2 + a3);
    double ab = 2.0 * x1 - (r == c ? 1.0 : 0.0);
    g_SD0[r * 64 + c] = ab;
    g_AbF[r * 64 + c] = (float)ab;
    red[c] = x1 * (double)B[c];
    __syncthreads();
    if (c == 0) {
        double s = 0.0;
        for (int i = 0; i < 64; ++i) s += red[i];
        g_BbF[r] = (float)(g_stepD[1] * s);
    }
}

// ------- kernel 4..12: fp64 squaring dst = src*src (64 blocks x 64 thr) -----
// emitT: 0 none, 1 -> g_M128T, 2 -> g_M512T (fp32 transpose of result)
__global__ __launch_bounds__(64) void k_sq(const double* __restrict__ src,
                                           double* __restrict__ dst, int emitT) {
    __shared__ double Ssh[4096];
    const int r = blockIdx.x, c = threadIdx.x;
    for (int i = c; i < 4096; i += 64) Ssh[i] = src[i];
    __syncthreads();
    double a0 = 0.0, a1 = 0.0, a2 = 0.0, a3 = 0.0;
    #pragma unroll 4
    for (int k = 0; k < 64; k += 4) {
        a0 += Ssh[r * 64 + k + 0] * Ssh[(k + 0) * 64 + c];
        a1 += Ssh[r * 64 + k + 1] * Ssh[(k + 1) * 64 + c];
        a2 += Ssh[r * 64 + k + 2] * Ssh[(k + 2) * 64 + c];
        a3 += Ssh[r * 64 + k + 3] * Ssh[(k + 3) * 64 + c];
    }
    double acc = (a0 + a1) + (a2 + a3);
    dst[r * 64 + c] = acc;
    if (emitT == 1) g_M128T[c * 64 + r] = (float)acc;
    else if (emitT == 2) g_M512T[c * 64 + r] = (float)acc;
}

// ------- kernel 13: W serial chain || V seeds + 4 chains (one block) --------
// dyn smem floats: AbS[4096] | M128T[4096] | M512T[4096] | wbuf[2*64] | vseed[4*64] | vbuf[4*2*64]
#define CH_SMEM_FLOATS (4096 * 3 + 128 + 256 + 512)
__global__ __launch_bounds__(320) void k_chains(const float* __restrict__ C) {
    extern __shared__ float sm[];
    float* AbS   = sm;
    float* M128S = sm + 4096;
    float* M512S = sm + 8192;
    float* wbuf  = sm + 12288;          // [2][64]
    float* vseed = sm + 12416;          // [4][64]
    float* vbuf  = sm + 12672;          // [4][2][64]
    const int tid = threadIdx.x;

    for (int i = tid; i < 4096; i += 320) AbS[i]   = g_AbF[i];
    for (int i = tid; i < 4096; i += 320) M128S[i] = g_M128T[i];
    for (int i = tid; i < 4096; i += 320) M512S[i] = g_M512T[i];
    __syncthreads();

    if (tid < 64) {
        // ---- W chain: W[0]=C, W[j] = W[j-1] * Ab ----
        const int c = tid;
        float w = C[c];
        wbuf[c] = w;
        g_W[c] = w;
        asm volatile("bar.sync 2, 64;" ::: "memory");
        int p = 0;
        for (int stp = 1; stp < 128; ++stp) {
            const float* wr = wbuf + p * 64;
            float a0 = 0.f, a1 = 0.f, a2 = 0.f, a3 = 0.f;
            #pragma unroll 16
            for (int r = 0; r < 64; r += 4) {
                a0 += wr[r + 0] * AbS[(r + 0) * 64 + c];
                a1 += wr[r + 1] * AbS[(r + 1) * 64 + c];
                a2 += wr[r + 2] * AbS[(r + 2) * 64 + c];
                a3 += wr[r + 3] * AbS[(r + 3) * 64 + c];
            }
            float nw = (a0 + a1) + (a2 + a3);
            wbuf[(1 - p) * 64 + c] = nw;
            g_W[stp * 64 + c] = nw;
            p ^= 1;
            asm volatile("bar.sync 2, 64;" ::: "memory");
        }
    } else {
        // ---- V: seeds V[0..3] via M128, then 4 chains stepped by M512 ----
        const int t = tid - 64;
        if (t < 64) {
            float v = g_BbF[t];
            vseed[t] = v;
            g_V[t] = v;
        }
        asm volatile("bar.sync 3, 256;" ::: "memory");
        for (int sd = 1; sd <= 3; ++sd) {
            float acc = 0.f;
            if (t < 64) {
                const float* vp = vseed + (sd - 1) * 64;
                float a0 = 0.f, a1 = 0.f, a2 = 0.f, a3 = 0.f;
                #pragma unroll 16
                for (int cc = 0; cc < 64; cc += 4) {
                    a0 += M128S[(cc + 0) * 64 + t] * vp[cc + 0];
                    a1 += M128S[(cc + 1) * 64 + t] * vp[cc + 1];
                    a2 += M128S[(cc + 2) * 64 + t] * vp[cc + 2];
                    a3 += M128S[(cc + 3) * 64 + t] * vp[cc + 3];
                }
                acc = (a0 + a1) + (a2 + a3);
            }
            asm volatile("bar.sync 3, 256;" ::: "memory");
            if (t < 64) {
                vseed[sd * 64 + t] = acc;
                g_V[sd * 64 + t] = acc;
            }
            asm volatile("bar.sync 3, 256;" ::: "memory");
        }
        const int ch = t >> 6, r = t & 63;
        vbuf[ch * 128 + r] = vseed[ch * 64 + r];
        asm volatile("bar.sync 3, 256;" ::: "memory");
        int p = 0;
        for (int sp = 1; sp <= 31; ++sp) {
            const float* vp = vbuf + ch * 128 + p * 64;
            float a0 = 0.f, a1 = 0.f, a2 = 0.f, a3 = 0.f;
            #pragma unroll 16
            for (int cc = 0; cc < 64; cc += 4) {
                a0 += M512S[(cc + 0) * 64 + r] * vp[cc + 0];
                a1 += M512S[(cc + 1) * 64 + r] * vp[cc + 1];
                a2 += M512S[(cc + 2) * 64 + r] * vp[cc + 2];
                a3 += M512S[(cc + 3) * 64 + r] * vp[cc + 3];
            }
            float acc = (a0 + a1) + (a2 + a3);
            vbuf[ch * 128 + (1 - p) * 64 + r] = acc;
            g_V[(ch + 4 * sp) * 64 + r] = acc;
            p ^= 1;
            asm volatile("bar.sync 3, 256;" ::: "memory");
        }
    }
}

// ---------------- kernel 14: K[128 i + j] = W[j] . V[i] ---------------------
__global__ __launch_bounds__(128) void k_K() {
    int il = blockIdx.x * 128 + threadIdx.x;
    int j = il & 127, i = il >> 7;
    float acc = 0.f;
    #pragma unroll 8
    for (int r = 0; r < 64; ++r) acc += g_W[j * 64 + r] * g_V[i * 64 + r];
    g_K[il] = acc;
}

// ---------------- kernel 15: H = rfft(K, 32768) / MF ------------------------
__global__ __launch_bounds__(T_FFT) void k_kfft() {
    extern __shared__ float2 sh2[];
    float2* s   = sh2;
    float2* tC  = s + 17408;
    float2* tF  = tC + 128;
    float2* tCN = tF + 128;
    float2* tFN = tCN + 128;
    const int tid = threadIdx.x;
    if (tid < 128) {
        tC[tid] = g_twC[tid]; tF[tid] = g_twF[tid];
        tCN[tid] = g_twCN[tid]; tFN[tid] = g_twFN[tid];
    }
    __syncthreads();
    fft_fwd(s, tC, tF, reinterpret_cast<const float2*>(g_K));

    const float sc = 1.0f / (float)MF;
    if (tid == 0) {
        float2 Z0 = s[PADI(0)];
        g_H[0]  = make_float2((Z0.x + Z0.y) * sc, 0.f);
        g_H[MF] = make_float2((Z0.x - Z0.y) * sc, 0.f);
    }
    for (int k = tid + 1; k <= HALF; k += T_FFT) {
        int rk = PADI(rev4_14(k));
        int rm = PADI(rev4_14(MF - k));
        float2 a  = s[rk];
        float2 bb = cconj(s[rm]);
        float2 E  = make_float2(0.5f * (a.x + bb.x), 0.5f * (a.y + bb.y));
        float2 Od = make_float2(0.5f * (a.x - bb.x), 0.5f * (a.y - bb.y));
        float2 wN = cmul(tCN[k >> 7], tFN[k & 127]);
        float2 g  = make_float2(wN.y, -wN.x);
        float2 gOd = cmul(g, Od);
        g_H[k]      = make_float2((E.x + gOd.x) * sc, (E.y + gOd.y) * sc);
        g_H[MF - k] = make_float2((E.x - gOd.x) * sc, -(E.y - gOd.y) * sc);
    }
}

// ---------------- kernel 16: per-row FFT conv + D*u -------------------------
__global__ __launch_bounds__(T_FFT) void k_conv(const float* __restrict__ u,
                                                const float* __restrict__ Dp,
                                                float* __restrict__ out) {
    extern __shared__ float2 sh2[];
    float2* s   = sh2;
    float2* tC  = s + 17408;
    float2* tF  = tC + 128;
    float2* tCN = tF + 128;
    float2* tFN = tCN + 128;
    const int tid = threadIdx.x;
    const int b = blockIdx.x;
    if (tid < 128) {
        tC[tid] = g_twC[tid]; tF[tid] = g_twF[tid];
        tCN[tid] = g_twCN[tid]; tFN[tid] = g_twFN[tid];
    }
    __syncthreads();

    const float2* u2 = reinterpret_cast<const float2*>(u) + (size_t)b * HALF;
    fft_fwd(s, tC, tF, u2);

    if (tid == 0) {
        float2 Z0 = s[PADI(0)];
        float X0 = Z0.x + Z0.y;
        float XM = Z0.x - Z0.y;
        float Y0 = X0 * g_H[0].x;
        float YM = XM * g_H[MF].x;
        s[PADI(0)] = make_float2(0.5f * (Y0 + YM), 0.5f * (Y0 - YM));
    }
    for (int k = tid + 1; k <= HALF; k += T_FFT) {
        int rk = PADI(rev4_14(k));
        int rm = PADI(rev4_14(MF - k));
        float2 a  = s[rk];
        float2 bb = cconj(s[rm]);
        float2 E  = make_float2(0.5f * (a.x + bb.x), 0.5f * (a.y + bb.y));
        float2 Od = make_float2(0.5f * (a.x - bb.x), 0.5f * (a.y - bb.y));
        float2 wN = cmul(tCN[k >> 7], tFN[k & 127]);
        float2 g  = make_float2(wN.y, -wN.x);
        float2 gOd = cmul(g, Od);
        float2 Xk = make_float2(E.x + gOd.x, E.y + gOd.y);
        float2 Xm = make_float2(E.x - gOd.x, -(E.y - gOd.y));
        float2 Yk = cmul(Xk, g_H[k]);
        float2 Ym = cmul(Xm, g_H[MF - k]);
        float2 cYm = cconj(Ym);
        float2 Ep  = make_float2(0.5f * (Yk.x + cYm.x), 0.5f * (Yk.y + cYm.y));
        float2 Dd  = make_float2(0.5f * (Yk.x - cYm.x), 0.5f * (Yk.y - cYm.y));
        float2 t1 = cmul(cconj(g), Dd);
        float2 t2 = cmul(g, cconj(Dd));
        s[rk] = make_float2(Ep.x + t1.x, Ep.y + t1.y);
        s[rm] = make_float2(Ep.x - t2.x, -Ep.y - t2.y);
    }
    __syncthreads();

    const float Dv = Dp[0];
    float2* o2 = reinterpret_cast<float2*>(out) + (size_t)b * HALF;
    fft_inv(s, tC, tF, o2, u2, Dv);
}

// ---------------- launch ----------------------------------------------------
extern "C" void kernel_launch(void* const* d_in, const int* in_sizes, int n_in,
                              void* d_out, int out_size) {
    const float* u  = (const float*)d_in[0];
    const float* A  = (const float*)d_in[1];
    const float* B  = (const float*)d_in[2];
    const float* C  = (const float*)d_in[3];
    const float* D  = (const float*)d_in[4];
    const float* ls = (const float*)d_in[5];
    float* out = (float*)d_out;

    const int smemFFT = (17408 + 4 * 128) * (int)sizeof(float2);   // 143360
    const int smemCh  = CH_SMEM_FLOATS * (int)sizeof(float);       // 52736

    cudaFuncSetAttribute(k_chains, cudaFuncAttributeMaxDynamicSharedMemorySize, smemCh);
    cudaFuncSetAttribute(k_kfft, cudaFuncAttributeMaxDynamicSharedMemorySize, smemFFT);
    cudaFuncSetAttribute(k_conv, cudaFuncAttributeMaxDynamicSharedMemorySize, smemFFT);

    double* SD0;  double* SD1;
    cudaGetSymbolAddress((void**)&SD0, g_SD0);
    cudaGetSymbolAddress((void**)&SD1, g_SD1);

    k_disc<<<1, 256>>>(A, ls);
    k_ref1<<<64, 64>>>(A);
    k_ref2<<<64, 64>>>(B);
    // squarings: Ab^2 .. Ab^512 (9), emit fp32 transposes at 128 and 512
    k_sq<<<64, 64>>>(SD0, SD1, 0);   // Ab^2
    k_sq<<<64, 64>>>(SD1, SD0, 0);   // Ab^4
    k_sq<<<64, 64>>>(SD0, SD1, 0);   // Ab^8
    k_sq<<<64, 64>>>(SD1, SD0, 0);   // Ab^16
    k_sq<<<64, 64>>>(SD0, SD1, 0);   // Ab^32
    k_sq<<<64, 64>>>(SD1, SD0, 0);   // Ab^64
    k_sq<<<64, 64>>>(SD0, SD1, 1);   // Ab^128  -> g_M128T
    k_sq<<<64, 64>>>(SD1, SD0, 0);   // Ab^256
    k_sq<<<64, 64>>>(SD0, SD1, 2);   // Ab^512  -> g_M512T
    k_chains<<<1, 320, smemCh>>>(C);
    k_K<<<128, 128>>>();
    k_kfft<<<1, T_FFT, smemFFT>>>();
    k_conv<<<512, T_FFT, smemFFT>>>(u, D, out);
}

// round 8
// speedup vs baseline: 2.7436x; 1.0471x over previous
#include <cuda_runtime.h>
#include <math.h>

#define T_FFT 512
#define LOG2M 14
#define MF    16384      // complex FFT length (real length N = 32768)
#define HALF  8192       // MF/2
#define LSEQ  16384
#define QB    4096       // MF/4 butterflies per radix-4 stage
#define PADI(i) ((i) + ((i) >> 4))

// ---------------- device scratch ----------------
__device__ float  g_W[128 * 64];
__device__ float  g_V[128 * 64];
__device__ float  g_K[LSEQ];
__device__ float2 g_H[MF + 1];
__device__ float2 g_twC[128];   // e^{-2pi i h/128}
__device__ float2 g_twF[128];   // e^{-2pi i l/16384}
__device__ float2 g_twCN[128];  // e^{-2pi i h/256}
__device__ float2 g_twFN[128];  // e^{-2pi i l/32768}

__device__ double g_SD0[4096];
__device__ double g_SD1[4096];
__device__ double g_RD[4096];
__device__ float  g_X0[4096];
__device__ float  g_AbF[4096];
__device__ float  g_M128T[4096];
__device__ float  g_M512T[4096];
__device__ float  g_BbF[64];
__device__ double g_stepD[2];   // hs, st
__device__ unsigned g_bar;      // grid-barrier counter (memset to 0 pre-launch)

__device__ __forceinline__ float2 cmul(float2 a, float2 b) {
    return make_float2(a.x * b.x - a.y * b.y, a.x * b.y + a.y * b.x);
}
__device__ __forceinline__ float2 cconj(float2 a) { return make_float2(a.x, -a.y); }
__device__ __forceinline__ float2 cadd(float2 a, float2 b) { return make_float2(a.x + b.x, a.y + b.y); }
__device__ __forceinline__ float2 csub(float2 a, float2 b) { return make_float2(a.x - b.x, a.y - b.y); }
__device__ __forceinline__ float2 cmulni(float2 a) { return make_float2(a.y, -a.x); }  // -i*a
__device__ __forceinline__ float2 cmuli(float2 a)  { return make_float2(-a.y, a.x); }  // +i*a

__device__ __forceinline__ float2 twid(const float2* tC, const float2* tF, int x) {
    return cmul(tC[x >> 7], tF[x & 127]);   // e^{-2pi i x / 16384}, x < 16384
}

__device__ __forceinline__ int rev4_14(int k) {
    unsigned br = __brev((unsigned)k) >> 18;
    return (int)(((br & 0x2AAAu) >> 1) | ((br & 0x1555u) << 1));
}

__constant__ float2 c_w16a[4] = {
    {1.0f, 0.0f}, {0.92387953251f, -0.38268343236f},
    {0.70710678119f, -0.70710678119f}, {0.38268343236f, -0.92387953251f}};
__constant__ float2 c_w16b[4] = {
    {1.0f, 0.0f}, {0.70710678119f, -0.70710678119f},
    {0.0f, -1.0f}, {-0.70710678119f, -0.70710678119f}};
__constant__ float2 c_w16c[4] = {
    {1.0f, 0.0f}, {0.38268343236f, -0.92387953251f},
    {-0.70710678119f, -0.70710678119f}, {-0.92387953251f, 0.38268343236f}};

// ---------- forward FFT: fused global-load first stage (upper half zero) ----
__device__ void fft_fwd(float2* s, const float2* tC, const float2* tF,
                        const float2* __restrict__ gin) {
    const int tid = threadIdx.x;
    #pragma unroll
    for (int it = 0; it < QB / T_FFT; ++it) {
        int q = tid + it * T_FFT;
        float2 a = gin[q];
        float2 b = gin[q + 4096];
        float2 w1 = twid(tC, tF, q);
        float2 w2 = twid(tC, tF, 2 * q);
        float2 w3 = twid(tC, tF, 3 * q);
        s[PADI(q)]         = cadd(a, b);
        s[PADI(q + 4096)]  = cmul(cadd(a, cmulni(b)), w1);
        s[PADI(q + 8192)]  = cmul(csub(a, b), w2);
        s[PADI(q + 12288)] = cmul(cadd(a, cmuli(b)), w3);
    }
    __syncthreads();
    #pragma unroll
    for (int st = 0; st < 4; ++st) {
        const int lg = 10 - 2 * st;
        const int H = 1 << lg;
        #pragma unroll
        for (int it = 0; it < QB / T_FFT; ++it) {
            int q = tid + it * T_FFT;
            int j = q & (H - 1);
            int i0 = ((q >> lg) << (lg + 2)) + j;
            float2 a = s[PADI(i0)], b = s[PADI(i0 + H)];
            float2 c = s[PADI(i0 + 2 * H)], d = s[PADI(i0 + 3 * H)];
            float2 y0 = cadd(a, c), y1 = csub(a, c);
            float2 y2 = cadd(b, d), y3 = csub(b, d);
            int x = j << (12 - lg);
            float2 w1 = twid(tC, tF, x);
            float2 w2 = twid(tC, tF, 2 * x);
            float2 w3 = twid(tC, tF, 3 * x);
            float2 m3 = cmulni(y3);
            s[PADI(i0)]         = cadd(y0, y2);
            s[PADI(i0 + H)]     = cmul(cadd(y1, m3), w1);
            s[PADI(i0 + 2 * H)] = cmul(csub(y0, y2), w2);
            s[PADI(i0 + 3 * H)] = cmul(csub(y1, m3), w3);
        }
        __syncthreads();
    }
    #pragma unroll
    for (int it = 0; it < (MF / 16) / T_FFT; ++it) {
        int m = tid + it * T_FFT;
        int base = 16 * m;
        float2 v[16];
        #pragma unroll
        for (int e = 0; e < 16; ++e) v[e] = s[PADI(base + e)];
        #pragma unroll
        for (int j = 0; j < 4; ++j) {
            float2 a = v[j], b = v[j + 4], c = v[j + 8], d = v[j + 12];
            float2 y0 = cadd(a, c), y1 = csub(a, c);
            float2 y2 = cadd(b, d), y3 = csub(b, d);
            float2 m3 = cmulni(y3);
            v[j]      = cadd(y0, y2);
            v[j + 4]  = cmul(cadd(y1, m3), c_w16a[j]);
            v[j + 8]  = cmul(csub(y0, y2), c_w16b[j]);
            v[j + 12] = cmul(csub(y1, m3), c_w16c[j]);
        }
        #pragma unroll
        for (int g = 0; g < 4; ++g) {
            float2 a = v[4 * g], b = v[4 * g + 1], c = v[4 * g + 2], d = v[4 * g + 3];
            float2 y0 = cadd(a, c), y1 = csub(a, c);
            float2 y2 = cadd(b, d), y3 = csub(b, d);
            float2 m3 = cmulni(y3);
            v[4 * g]     = cadd(y0, y2);
            v[4 * g + 1] = cadd(y1, m3);
            v[4 * g + 2] = csub(y0, y2);
            v[4 * g + 3] = csub(y1, m3);
        }
        #pragma unroll
        for (int e = 0; e < 16; ++e) s[PADI(base + e)] = v[e];
    }
    __syncthreads();
}

// ---------- inverse FFT: fused last stage writes z + D*u directly to gmem ---
__device__ void fft_inv(float2* s, const float2* tC, const float2* tF,
                        float2* __restrict__ gout, const float2* __restrict__ gu,
                        float Dv) {
    const int tid = threadIdx.x;
    #pragma unroll
    for (int it = 0; it < (MF / 16) / T_FFT; ++it) {
        int m = tid + it * T_FFT;
        int base = 16 * m;
        float2 v[16];
        #pragma unroll
        for (int e = 0; e < 16; ++e) v[e] = s[PADI(base + e)];
        #pragma unroll
        for (int g = 0; g < 4; ++g) {
            float2 b0 = v[4 * g], b1 = v[4 * g + 1], b2 = v[4 * g + 2], b3 = v[4 * g + 3];
            float2 y0 = cadd(b0, b2), y1 = csub(b0, b2);
            float2 y2 = cadd(b1, b3), y3 = cmuli(csub(b1, b3));
            v[4 * g]     = cadd(y0, y2);
            v[4 * g + 1] = cadd(y1, y3);
            v[4 * g + 2] = csub(y0, y2);
            v[4 * g + 3] = csub(y1, y3);
        }
        #pragma unroll
        for (int j = 0; j < 4; ++j) {
            float2 b0 = v[j];
            float2 t1 = cmul(v[j + 4],  cconj(c_w16a[j]));
            float2 t2 = cmul(v[j + 8],  cconj(c_w16b[j]));
            float2 t3 = cmul(v[j + 12], cconj(c_w16c[j]));
            float2 y0 = cadd(b0, t2), y1 = csub(b0, t2);
            float2 y2 = cadd(t1, t3), y3 = cmuli(csub(t1, t3));
            v[j]      = cadd(y0, y2);
            v[j + 4]  = cadd(y1, y3);
            v[j + 8]  = csub(y0, y2);
            v[j + 12] = csub(y1, y3);
        }
        #pragma unroll
        for (int e = 0; e < 16; ++e) s[PADI(base + e)] = v[e];
    }
    __syncthreads();
    #pragma unroll
    for (int st = 0; st < 4; ++st) {
        const int lg = 4 + 2 * st;
        const int H = 1 << lg;
        #pragma unroll
        for (int it = 0; it < QB / T_FFT; ++it) {
            int q = tid + it * T_FFT;
            int j = q & (H - 1);
            int i0 = ((q >> lg) << (lg + 2)) + j;
            int x = j << (12 - lg);
            float2 w1 = cconj(twid(tC, tF, x));
            float2 w2 = cconj(twid(tC, tF, 2 * x));
            float2 w3 = cconj(twid(tC, tF, 3 * x));
            float2 b0 = s[PADI(i0)];
            float2 t1 = cmul(s[PADI(i0 + H)], w1);
            float2 t2 = cmul(s[PADI(i0 + 2 * H)], w2);
            float2 t3 = cmul(s[PADI(i0 + 3 * H)], w3);
            float2 y0 = cadd(b0, t2), y1 = csub(b0, t2);
            float2 y2 = cadd(t1, t3), y3 = cmuli(csub(t1, t3));
            s[PADI(i0)]         = cadd(y0, y2);
            s[PADI(i0 + H)]     = cadd(y1, y3);
            s[PADI(i0 + 2 * H)] = csub(y0, y2);
            s[PADI(i0 + 3 * H)] = csub(y1, y3);
        }
        __syncthreads();
    }
    #pragma unroll
    for (int it = 0; it < QB / T_FFT; ++it) {
        int q = tid + it * T_FFT;
        float2 w1 = cconj(twid(tC, tF, q));
        float2 w2 = cconj(twid(tC, tF, 2 * q));
        float2 w3 = cconj(twid(tC, tF, 3 * q));
        float2 b0 = s[PADI(q)];
        float2 t1 = cmul(s[PADI(q + 4096)], w1);
        float2 t2 = cmul(s[PADI(q + 8192)], w2);
        float2 t3 = cmul(s[PADI(q + 12288)], w3);
        float2 y0 = cadd(b0, t2), y1 = csub(b0, t2);
        float2 y2 = cadd(t1, t3), y3 = cmuli(csub(t1, t3));
        float2 z0 = cadd(y0, y2);
        float2 z1 = cadd(y1, y3);
        float2 u0 = gu[q], u1 = gu[q + 4096];
        gout[q]        = make_float2(z0.x + Dv * u0.x, z0.y + Dv * u0.y);
        gout[q + 4096] = make_float2(z1.x + Dv * u1.x, z1.y + Dv * u1.y);
    }
}

// ------- kernel 1: twiddles + steps + fp32 Gauss-Jordan inverse of M --------
__global__ __launch_bounds__(256) void k_disc(const float* __restrict__ A,
                                              const float* __restrict__ logstep) {
    __shared__ float aug[64 * 132];   // [M | I], padded width
    __shared__ float fcol[64];
    __shared__ float sinv;
    const int tid = threadIdx.x;

    if (tid < 128) {
        const double PI = 3.14159265358979323846;
        double sv, cv, ang;
        ang = -2.0 * PI * (double)tid / 128.0;    sincos(ang, &sv, &cv);
        g_twC[tid] = make_float2((float)cv, (float)sv);
        ang = -2.0 * PI * (double)tid / 16384.0;  sincos(ang, &sv, &cv);
        g_twF[tid] = make_float2((float)cv, (float)sv);
        ang = -2.0 * PI * (double)tid / 256.0;    sincos(ang, &sv, &cv);
        g_twCN[tid] = make_float2((float)cv, (float)sv);
        ang = -2.0 * PI * (double)tid / 32768.0;  sincos(ang, &sv, &cv);
        g_twFN[tid] = make_float2((float)cv, (float)sv);
    }
    if (tid == 0) {
        float stf = (float)exp((double)logstep[0]);  // match ref's fp32 step
        g_stepD[0] = 0.5 * (double)stf;
        g_stepD[1] = (double)stf;
    }
    __syncthreads();
    const float hs = (float)g_stepD[0];

    for (int idx = tid; idx < 64 * 128; idx += 256) {
        int r = idx >> 7, c = idx & 127;
        float v;
        if (c < 64) v = (r == c ? 1.f : 0.f) - hs * A[r * 64 + c];
        else        v = (r == (c - 64)) ? 1.f : 0.f;
        aug[r * 132 + c] = v;
    }
    __syncthreads();

    const int gr  = tid >> 2;
    const int gc0 = tid & 3;
    for (int col = 0; col < 64; ++col) {
        if (tid == 0) sinv = 1.0f / aug[col * 132 + col];
        __syncthreads();
        float inv = sinv;
        for (int c = tid; c < 128; c += 256) aug[col * 132 + c] *= inv;
        if (tid < 64) fcol[tid] = (tid == col) ? 0.f : aug[tid * 132 + col];
        __syncthreads();
        float f = fcol[gr];
        for (int c = gc0; c < 128; c += 4)
            aug[gr * 132 + c] -= f * aug[col * 132 + c];
        __syncthreads();
    }

    for (int idx = tid; idx < 4096; idx += 256) {
        int r = idx >> 6, c = idx & 63;
        g_X0[idx] = aug[r * 132 + 64 + c];
    }
}

// ------- grid barrier (64-block single wave; counter pre-zeroed) ------------
__device__ __forceinline__ void grid_bar(unsigned phase) {
    __syncthreads();
    if (threadIdx.x == 0) {
        __threadfence();
        atomicAdd(&g_bar, 1u);
        const unsigned target = phase * 64u;
        while (atomicAdd(&g_bar, 0u) < target) { }
    }
    __syncthreads();
}

// ------- kernel 2: persistent — Newton refine + 9 fp64 squarings ------------
// 64 blocks x 64 threads, one wave. All cross-phase gmem traffic uses ldcg/stcg.
__global__ __launch_bounds__(64) void k_power(const float* __restrict__ A,
                                              const float* __restrict__ B) {
    extern __shared__ char pmem[];
    float*  X0s = reinterpret_cast<float*>(pmem);    // 16 KB (phases A/B)
    double* Ssh = reinterpret_cast<double*>(pmem);   // 32 KB (squaring phases)
    __shared__ double red[64];
    const int r = blockIdx.x, c = threadIdx.x;
    unsigned phase = 0;

    for (int i = c; i < 4096; i += 64) X0s[i] = g_X0[i];
    __syncthreads();
    const double hs = g_stepD[0];
    const double st = g_stepD[1];

    // phase A: R = I - M*X0 (row r)
    {
        double a0 = 0.0, a1 = 0.0;
        #pragma unroll 8
        for (int k = 0; k < 64; k += 2) {
            double m0 = (r == k     ? 1.0 : 0.0) - hs * (double)A[r * 64 + k];
            double m1 = (r == k + 1 ? 1.0 : 0.0) - hs * (double)A[r * 64 + k + 1];
            a0 += m0 * (double)X0s[k * 64 + c];
            a1 += m1 * (double)X0s[(k + 1) * 64 + c];
        }
        g_RD[r * 64 + c] = (r == c ? 1.0 : 0.0) - (a0 + a1);
    }
    grid_bar(++phase);

    // phase B: X1 = X0 + X0*R ; Ab = 2*X1 - I ; Bb = st * X1 * B
    {
        double a0 = 0.0, a1 = 0.0;
        #pragma unroll 8
        for (int k = 0; k < 64; k += 2) {
            a0 += (double)X0s[r * 64 + k]     * __ldcg(&g_RD[k * 64 + c]);
            a1 += (double)X0s[r * 64 + k + 1] * __ldcg(&g_RD[(k + 1) * 64 + c]);
        }
        double x1 = (double)X0s[r * 64 + c] + (a0 + a1);
        double ab = 2.0 * x1 - (r == c ? 1.0 : 0.0);
        __stcg(&g_SD0[r * 64 + c], ab);
        g_AbF[r * 64 + c] = (float)ab;
        red[c] = x1 * (double)B[c];
        __syncthreads();
        if (c == 0) {
            double s = 0.0;
            for (int i = 0; i < 64; ++i) s += red[i];
            g_BbF[r] = (float)(st * s);
        }
    }
    grid_bar(++phase);   // also fences smem aliasing X0s -> Ssh

    // phases C0..C8: 9 squarings; t=6 emits M128T, t=8 emits M512T
    for (int t = 0; t < 9; ++t) {
        const double* src = (t & 1) ? g_SD1 : g_SD0;
        double*       dst = (t & 1) ? g_SD0 : g_SD1;
        const double2* s2 = reinterpret_cast<const double2*>(src);
        double2* h2 = reinterpret_cast<double2*>(Ssh);
        for (int i = c; i < 2048; i += 64) h2[i] = __ldcg(&s2[i]);
        __syncthreads();
        double a0 = 0.0, a1 = 0.0, a2 = 0.0, a3 = 0.0;
        #pragma unroll 8
        for (int k = 0; k < 64; k += 4) {
            a0 += Ssh[r * 64 + k + 0] * Ssh[(k + 0) * 64 + c];
            a1 += Ssh[r * 64 + k + 1] * Ssh[(k + 1) * 64 + c];
            a2 += Ssh[r * 64 + k + 2] * Ssh[(k + 2) * 64 + c];
            a3 += Ssh[r * 64 + k + 3] * Ssh[(k + 3) * 64 + c];
        }
        double acc = (a0 + a1) + (a2 + a3);
        __stcg(&dst[r * 64 + c], acc);
        if (t == 6) g_M128T[c * 64 + r] = (float)acc;
        else if (t == 8) g_M512T[c * 64 + r] = (float)acc;
        if (t < 8) grid_bar(++phase);
        else { __syncthreads(); }   // protect smem before loop exit (no reuse after)
    }
}

// ------- kernel 3: W serial chain || V seeds + 4 chains (one block) ---------
#define CH_SMEM_FLOATS (4096 * 3 + 128 + 256 + 512)
__global__ __launch_bounds__(320) void k_chains(const float* __restrict__ C) {
    extern __shared__ float sm[];
    float* AbS   = sm;
    float* M128S = sm + 4096;
    float* M512S = sm + 8192;
    float* wbuf  = sm + 12288;          // [2][64]
    float* vseed = sm + 12416;          // [4][64]
    float* vbuf  = sm + 12672;          // [4][2][64]
    const int tid = threadIdx.x;

    for (int i = tid; i < 4096; i += 320) AbS[i]   = g_AbF[i];
    for (int i = tid; i < 4096; i += 320) M128S[i] = g_M128T[i];
    for (int i = tid; i < 4096; i += 320) M512S[i] = g_M512T[i];
    __syncthreads();

    if (tid < 64) {
        const int c = tid;
        float w = C[c];
        wbuf[c] = w;
        g_W[c] = w;
        asm volatile("bar.sync 2, 64;" ::: "memory");
        int p = 0;
        for (int stp = 1; stp < 128; ++stp) {
            const float* wr = wbuf + p * 64;
            float a0 = 0.f, a1 = 0.f, a2 = 0.f, a3 = 0.f;
            #pragma unroll 16
            for (int r = 0; r < 64; r += 4) {
                a0 += wr[r + 0] * AbS[(r + 0) * 64 + c];
                a1 += wr[r + 1] * AbS[(r + 1) * 64 + c];
                a2 += wr[r + 2] * AbS[(r + 2) * 64 + c];
                a3 += wr[r + 3] * AbS[(r + 3) * 64 + c];
            }
            float nw = (a0 + a1) + (a2 + a3);
            wbuf[(1 - p) * 64 + c] = nw;
            g_W[stp * 64 + c] = nw;
            p ^= 1;
            asm volatile("bar.sync 2, 64;" ::: "memory");
        }
    } else {
        const int t = tid - 64;
        if (t < 64) {
            float v = g_BbF[t];
            vseed[t] = v;
            g_V[t] = v;
        }
        asm volatile("bar.sync 3, 256;" ::: "memory");
        for (int sd = 1; sd <= 3; ++sd) {
            float acc = 0.f;
            if (t < 64) {
                const float* vp = vseed + (sd - 1) * 64;
                float a0 = 0.f, a1 = 0.f, a2 = 0.f, a3 = 0.f;
                #pragma unroll 16
                for (int cc = 0; cc < 64; cc += 4) {
                    a0 += M128S[(cc + 0) * 64 + t] * vp[cc + 0];
                    a1 += M128S[(cc + 1) * 64 + t] * vp[cc + 1];
                    a2 += M128S[(cc + 2) * 64 + t] * vp[cc + 2];
                    a3 += M128S[(cc + 3) * 64 + t] * vp[cc + 3];
                }
                acc = (a0 + a1) + (a2 + a3);
            }
            asm volatile("bar.sync 3, 256;" ::: "memory");
            if (t < 64) {
                vseed[sd * 64 + t] = acc;
                g_V[sd * 64 + t] = acc;
            }
            asm volatile("bar.sync 3, 256;" ::: "memory");
        }
        const int ch = t >> 6, r = t & 63;
        vbuf[ch * 128 + r] = vseed[ch * 64 + r];
        asm volatile("bar.sync 3, 256;" ::: "memory");
        int p = 0;
        for (int sp = 1; sp <= 31; ++sp) {
            const float* vp = vbuf + ch * 128 + p * 64;
            float a0 = 0.f, a1 = 0.f, a2 = 0.f, a3 = 0.f;
            #pragma unroll 16
            for (int cc = 0; cc < 64; cc += 4) {
                a0 += M512S[(cc + 0) * 64 + r] * vp[cc + 0];
                a1 += M512S[(cc + 1) * 64 + r] * vp[cc + 1];
                a2 += M512S[(cc + 2) * 64 + r] * vp[cc + 2];
                a3 += M512S[(cc + 3) * 64 + r] * vp[cc + 3];
            }
            float acc = (a0 + a1) + (a2 + a3);
            vbuf[ch * 128 + (1 - p) * 64 + r] = acc;
            g_V[(ch + 4 * sp) * 64 + r] = acc;
            p ^= 1;
            asm volatile("bar.sync 3, 256;" ::: "memory");
        }
    }
}

// ---------------- kernel 4: K[128 i + j] = W[j] . V[i] ----------------------
__global__ __launch_bounds__(128) void k_K() {
    int il = blockIdx.x * 128 + threadIdx.x;
    int j = il & 127, i = il >> 7;
    float acc = 0.f;
    #pragma unroll 8
    for (int r = 0; r < 64; ++r) acc += g_W[j * 64 + r] * g_V[i * 64 + r];
    g_K[il] = acc;
}

// ---------------- kernel 5: H = rfft(K, 32768) / MF -------------------------
__global__ __launch_bounds__(T_FFT) void k_kfft() {
    extern __shared__ float2 sh2[];
    float2* s   = sh2;
    float2* tC  = s + 17408;
    float2* tF  = tC + 128;
    float2* tCN = tF + 128;
    float2* tFN = tCN + 128;
    const int tid = threadIdx.x;
    if (tid < 128) {
        tC[tid] = g_twC[tid]; tF[tid] = g_twF[tid];
        tCN[tid] = g_twCN[tid]; tFN[tid] = g_twFN[tid];
    }
    __syncthreads();
    fft_fwd(s, tC, tF, reinterpret_cast<const float2*>(g_K));

    const float sc = 1.0f / (float)MF;
    if (tid == 0) {
        float2 Z0 = s[PADI(0)];
        g_H[0]  = make_float2((Z0.x + Z0.y) * sc, 0.f);
        g_H[MF] = make_float2((Z0.x - Z0.y) * sc, 0.f);
    }
    for (int k = tid + 1; k <= HALF; k += T_FFT) {
        int rk = PADI(rev4_14(k));
        int rm = PADI(rev4_14(MF - k));
        float2 a  = s[rk];
        float2 bb = cconj(s[rm]);
        float2 E  = make_float2(0.5f * (a.x + bb.x), 0.5f * (a.y + bb.y));
        float2 Od = make_float2(0.5f * (a.x - bb.x), 0.5f * (a.y - bb.y));
        float2 wN = cmul(tCN[k >> 7], tFN[k & 127]);
        float2 g  = make_float2(wN.y, -wN.x);
        float2 gOd = cmul(g, Od);
        g_H[k]      = make_float2((E.x + gOd.x) * sc, (E.y + gOd.y) * sc);
        g_H[MF - k] = make_float2((E.x - gOd.x) * sc, -(E.y - gOd.y) * sc);
    }
}

// ---------------- kernel 6: per-row FFT conv + D*u --------------------------
__global__ __launch_bounds__(T_FFT) void k_conv(const float* __restrict__ u,
                                                const float* __restrict__ Dp,
                                                float* __restrict__ out) {
    extern __shared__ float2 sh2[];
    float2* s   = sh2;
    float2* tC  = s + 17408;
    float2* tF  = tC + 128;
    float2* tCN = tF + 128;
    float2* tFN = tCN + 128;
    const int tid = threadIdx.x;
    const int b = blockIdx.x;
    if (tid < 128) {
        tC[tid] = g_twC[tid]; tF[tid] = g_twF[tid];
        tCN[tid] = g_twCN[tid]; tFN[tid] = g_twFN[tid];
    }
    __syncthreads();

    const float2* u2 = reinterpret_cast<const float2*>(u) + (size_t)b * HALF;
    fft_fwd(s, tC, tF, u2);

    if (tid == 0) {
        float2 Z0 = s[PADI(0)];
        float X0 = Z0.x + Z0.y;
        float XM = Z0.x - Z0.y;
        float Y0 = X0 * g_H[0].x;
        float YM = XM * g_H[MF].x;
        s[PADI(0)] = make_float2(0.5f * (Y0 + YM), 0.5f * (Y0 - YM));
    }
    for (int k = tid + 1; k <= HALF; k += T_FFT) {
        int rk = PADI(rev4_14(k));
        int rm = PADI(rev4_14(MF - k));
        float2 a  = s[rk];
        float2 bb = cconj(s[rm]);
        float2 E  = make_float2(0.5f * (a.x + bb.x), 0.5f * (a.y + bb.y));
        float2 Od = make_float2(0.5f * (a.x - bb.x), 0.5f * (a.y - bb.y));
        float2 wN = cmul(tCN[k >> 7], tFN[k & 127]);
        float2 g  = make_float2(wN.y, -wN.x);
        float2 gOd = cmul(g, Od);
        float2 Xk = make_float2(E.x + gOd.x, E.y + gOd.y);
        float2 Xm = make_float2(E.x - gOd.x, -(E.y - gOd.y));
        float2 Yk = cmul(Xk, g_H[k]);
        float2 Ym = cmul(Xm, g_H[MF - k]);
        float2 cYm = cconj(Ym);
        float2 Ep  = make_float2(0.5f * (Yk.x + cYm.x), 0.5f * (Yk.y + cYm.y));
        float2 Dd  = make_float2(0.5f * (Yk.x - cYm.x), 0.5f * (Yk.y - cYm.y));
        float2 t1 = cmul(cconj(g), Dd);
        float2 t2 = cmul(g, cconj(Dd));
        s[rk] = make_float2(Ep.x + t1.x, Ep.y + t1.y);
        s[rm] = make_float2(Ep.x - t2.x, -Ep.y - t2.y);
    }
    __syncthreads();

    const float Dv = Dp[0];
    float2* o2 = reinterpret_cast<float2*>(out) + (size_t)b * HALF;
    fft_inv(s, tC, tF, o2, u2, Dv);
}

// ---------------- launch ----------------------------------------------------
extern "C" void kernel_launch(void* const* d_in, const int* in_sizes, int n_in,
                              void* d_out, int out_size) {
    const float* u  = (const float*)d_in[0];
    const float* A  = (const float*)d_in[1];
    const float* B  = (const float*)d_in[2];
    const float* C  = (const float*)d_in[3];
    const float* D  = (const float*)d_in[4];
    const float* ls = (const float*)d_in[5];
    float* out = (float*)d_out;

    const int smemFFT = (17408 + 4 * 128) * (int)sizeof(float2);   // 143360
    const int smemCh  = CH_SMEM_FLOATS * (int)sizeof(float);       // 52736
    const int smemPw  = 4096 * (int)sizeof(double);                // 32768

    cudaFuncSetAttribute(k_chains, cudaFuncAttributeMaxDynamicSharedMemorySize, smemCh);
    cudaFuncSetAttribute(k_kfft, cudaFuncAttributeMaxDynamicSharedMemorySize, smemFFT);
    cudaFuncSetAttribute(k_conv, cudaFuncAttributeMaxDynamicSharedMemorySize, smemFFT);

    void* barp = nullptr;
    cudaGetSymbolAddress(&barp, g_bar);
    cudaMemsetAsync(barp, 0, sizeof(unsigned));

    k_disc<<<1, 256>>>(A, ls);
    k_power<<<64, 64, smemPw>>>(A, B);
    k_chains<<<1, 320, smemCh>>>(C);
    k_K<<<128, 128>>>();
    k_kfft<<<1, T_FFT, smemFFT>>>();
    k_conv<<<512, T_FFT, smemFFT>>>(u, D, out);
}

// round 13
// speedup vs baseline: 2.8338x; 1.0329x over previous
#include <cuda_runtime.h>
#include <math.h>

#define T_FFT 512
#define LOG2M 14
#define MF    16384      // complex FFT length (real length N = 32768)
#define HALF  8192       // MF/2
#define LSEQ  16384
#define QB    4096       // MF/4 butterflies per radix-4 stage
#define PADI(i) ((i) + ((i) >> 4))

// ---------------- device scratch ----------------
__device__ float  g_W[128 * 64];
__device__ float  g_V[128 * 64];
__device__ float  g_K[LSEQ];
__device__ float2 g_H[MF + 1];
__device__ float2 g_twC[128];   // e^{-2pi i h/128}
__device__ float2 g_twF[128];   // e^{-2pi i l/16384}
__device__ float2 g_twCN[128];  // e^{-2pi i h/256}
__device__ float2 g_twFN[128];  // e^{-2pi i l/32768}

__device__ float  g_X0[4096];
__device__ float  g_RF[4096];                 // fp32 Newton residual
__device__ float  g_DH0[4096], g_DL0[4096];   // df ping-pong (hi, lo)
__device__ float  g_DH1[4096], g_DL1[4096];
__device__ float  g_AbF[4096];
__device__ float  g_M128T[4096];
__device__ float  g_M512T[4096];
__device__ float  g_BbF[64];
__device__ double g_stepD[2];   // hs, st
__device__ unsigned g_bar;      // grid-barrier counter (memset to 0 pre-launch)

__device__ __forceinline__ float2 cmul(float2 a, float2 b) {
    return make_float2(a.x * b.x - a.y * b.y, a.x * b.y + a.y * b.x);
}
__device__ __forceinline__ float2 cconj(float2 a) { return make_float2(a.x, -a.y); }
__device__ __forceinline__ float2 cadd(float2 a, float2 b) { return make_float2(a.x + b.x, a.y + b.y); }
__device__ __forceinline__ float2 csub(float2 a, float2 b) { return make_float2(a.x - b.x, a.y - b.y); }
__device__ __forceinline__ float2 cmulni(float2 a) { return make_float2(a.y, -a.x); }  // -i*a
__device__ __forceinline__ float2 cmuli(float2 a)  { return make_float2(-a.y, a.x); }  // +i*a

__device__ __forceinline__ float2 twid(const float2* tC, const float2* tF, int x) {
    return cmul(tC[x >> 7], tF[x & 127]);   // e^{-2pi i x / 16384}, x < 16384
}

__device__ __forceinline__ int rev4_14(int k) {
    unsigned br = __brev((unsigned)k) >> 18;
    return (int)(((br & 0x2AAAu) >> 1) | ((br & 0x1555u) << 1));
}

__constant__ float2 c_w16a[4] = {
    {1.0f, 0.0f}, {0.92387953251f, -0.38268343236f},
    {0.70710678119f, -0.70710678119f}, {0.38268343236f, -0.92387953251f}};
__constant__ float2 c_w16b[4] = {
    {1.0f, 0.0f}, {0.70710678119f, -0.70710678119f},
    {0.0f, -1.0f}, {-0.70710678119f, -0.70710678119f}};
__constant__ float2 c_w16c[4] = {
    {1.0f, 0.0f}, {0.38268343236f, -0.92387953251f},
    {-0.70710678119f, -0.70710678119f}, {-0.92387953251f, 0.38268343236f}};

// ---------------- double-float (2x fp32) helpers ----------------
__device__ __forceinline__ float2 df_two_sum(float a, float b) {
    float s  = __fadd_rn(a, b);
    float bb = __fsub_rn(s, a);
    float e  = __fadd_rn(__fsub_rn(a, __fsub_rn(s, bb)), __fsub_rn(b, bb));
    return make_float2(s, e);
}
__device__ __forceinline__ float2 df_mul(float2 a, float2 b) {
    float p = __fmul_rn(a.x, b.x);
    float e = fmaf(a.x, b.x, -p);
    e = __fadd_rn(e, __fadd_rn(__fmul_rn(a.x, b.y), __fmul_rn(a.y, b.x)));
    return df_two_sum(p, e);
}
__device__ __forceinline__ float2 df_mul_f(float2 a, float b) {
    float p = __fmul_rn(a.x, b);
    float e = fmaf(a.x, b, -p);
    e = __fadd_rn(e, __fmul_rn(a.y, b));
    return df_two_sum(p, e);
}
__device__ __forceinline__ float2 df_add(float2 a, float2 b) {
    float2 s = df_two_sum(a.x, b.x);
    float e  = __fadd_rn(s.y, __fadd_rn(a.y, b.y));
    return df_two_sum(s.x, e);
}

// ---------- forward FFT: fused global-load first stage (upper half zero) ----
__device__ void fft_fwd(float2* s, const float2* tC, const float2* tF,
                        const float2* __restrict__ gin) {
    const int tid = threadIdx.x;
    #pragma unroll
    for (int it = 0; it < QB / T_FFT; ++it) {
        int q = tid + it * T_FFT;
        float2 a = gin[q];
        float2 b = gin[q + 4096];
        float2 w1 = twid(tC, tF, q);
        float2 w2 = twid(tC, tF, 2 * q);
        float2 w3 = twid(tC, tF, 3 * q);
        s[PADI(q)]         = cadd(a, b);
        s[PADI(q + 4096)]  = cmul(cadd(a, cmulni(b)), w1);
        s[PADI(q + 8192)]  = cmul(csub(a, b), w2);
        s[PADI(q + 12288)] = cmul(cadd(a, cmuli(b)), w3);
    }
    __syncthreads();
    #pragma unroll
    for (int st = 0; st < 4; ++st) {
        const int lg = 10 - 2 * st;
        const int H = 1 << lg;
        #pragma unroll
        for (int it = 0; it < QB / T_FFT; ++it) {
            int q = tid + it * T_FFT;
            int j = q & (H - 1);
            int i0 = ((q >> lg) << (lg + 2)) + j;
            float2 a = s[PADI(i0)], b = s[PADI(i0 + H)];
            float2 c = s[PADI(i0 + 2 * H)], d = s[PADI(i0 + 3 * H)];
            float2 y0 = cadd(a, c), y1 = csub(a, c);
            float2 y2 = cadd(b, d), y3 = csub(b, d);
            int x = j << (12 - lg);
            float2 w1 = twid(tC, tF, x);
            float2 w2 = twid(tC, tF, 2 * x);
            float2 w3 = twid(tC, tF, 3 * x);
            float2 m3 = cmulni(y3);
            s[PADI(i0)]         = cadd(y0, y2);
            s[PADI(i0 + H)]     = cmul(cadd(y1, m3), w1);
            s[PADI(i0 + 2 * H)] = cmul(csub(y0, y2), w2);
            s[PADI(i0 + 3 * H)] = cmul(csub(y1, m3), w3);
        }
        __syncthreads();
    }
    #pragma unroll
    for (int it = 0; it < (MF / 16) / T_FFT; ++it) {
        int m = tid + it * T_FFT;
        int base = 16 * m;
        float2 v[16];
        #pragma unroll
        for (int e = 0; e < 16; ++e) v[e] = s[PADI(base + e)];
        #pragma unroll
        for (int j = 0; j < 4; ++j) {
            float2 a = v[j], b = v[j + 4], c = v[j + 8], d = v[j + 12];
            float2 y0 = cadd(a, c), y1 = csub(a, c);
            float2 y2 = cadd(b, d), y3 = csub(b, d);
            float2 m3 = cmulni(y3);
            v[j]      = cadd(y0, y2);
            v[j + 4]  = cmul(cadd(y1, m3), c_w16a[j]);
            v[j + 8]  = cmul(csub(y0, y2), c_w16b[j]);
            v[j + 12] = cmul(csub(y1, m3), c_w16c[j]);
        }
        #pragma unroll
        for (int g = 0; g < 4; ++g) {
            float2 a = v[4 * g], b = v[4 * g + 1], c = v[4 * g + 2], d = v[4 * g + 3];
            float2 y0 = cadd(a, c), y1 = csub(a, c);
            float2 y2 = cadd(b, d), y3 = csub(b, d);
            float2 m3 = cmulni(y3);
            v[4 * g]     = cadd(y0, y2);
            v[4 * g + 1] = cadd(y1, m3);
            v[4 * g + 2] = csub(y0, y2);
            v[4 * g + 3] = csub(y1, m3);
        }
        #pragma unroll
        for (int e = 0; e < 16; ++e) s[PADI(base + e)] = v[e];
    }
    __syncthreads();
}

// ---------- inverse FFT: fused last stage writes z + D*u directly to gmem ---
__device__ void fft_inv(float2* s, const float2* tC, const float2* tF,
                        float2* __restrict__ gout, const float2* __restrict__ gu,
                        float Dv) {
    const int tid = threadIdx.x;
    #pragma unroll
    for (int it = 0; it < (MF / 16) / T_FFT; ++it) {
        int m = tid + it * T_FFT;
        int base = 16 * m;
        float2 v[16];
        #pragma unroll
        for (int e = 0; e < 16; ++e) v[e] = s[PADI(base + e)];
        #pragma unroll
        for (int g = 0; g < 4; ++g) {
            float2 b0 = v[4 * g], b1 = v[4 * g + 1], b2 = v[4 * g + 2], b3 = v[4 * g + 3];
            float2 y0 = cadd(b0, b2), y1 = csub(b0, b2);
            float2 y2 = cadd(b1, b3), y3 = cmuli(csub(b1, b3));
            v[4 * g]     = cadd(y0, y2);
            v[4 * g + 1] = cadd(y1, y3);
            v[4 * g + 2] = csub(y0, y2);
            v[4 * g + 3] = csub(y1, y3);
        }
        #pragma unroll
        for (int j = 0; j < 4; ++j) {
            float2 b0 = v[j];
            float2 t1 = cmul(v[j + 4],  cconj(c_w16a[j]));
            float2 t2 = cmul(v[j + 8],  cconj(c_w16b[j]));
            float2 t3 = cmul(v[j + 12], cconj(c_w16c[j]));
            float2 y0 = cadd(b0, t2), y1 = csub(b0, t2);
            float2 y2 = cadd(t1, t3), y3 = cmuli(csub(t1, t3));
            v[j]      = cadd(y0, y2);
            v[j + 4]  = cadd(y1, y3);
            v[j + 8]  = csub(y0, y2);
            v[j + 12] = csub(y1, y3);
        }
        #pragma unroll
        for (int e = 0; e < 16; ++e) s[PADI(base + e)] = v[e];
    }
    __syncthreads();
    #pragma unroll
    for (int st = 0; st < 4; ++st) {
        const int lg = 4 + 2 * st;
        const int H = 1 << lg;
        #pragma unroll
        for (int it = 0; it < QB / T_FFT; ++it) {
            int q = tid + it * T_FFT;
            int j = q & (H - 1);
            int i0 = ((q >> lg) << (lg + 2)) + j;
            int x = j << (12 - lg);
            float2 w1 = cconj(twid(tC, tF, x));
            float2 w2 = cconj(twid(tC, tF, 2 * x));
            float2 w3 = cconj(twid(tC, tF, 3 * x));
            float2 b0 = s[PADI(i0)];
            float2 t1 = cmul(s[PADI(i0 + H)], w1);
            float2 t2 = cmul(s[PADI(i0 + 2 * H)], w2);
            float2 t3 = cmul(s[PADI(i0 + 3 * H)], w3);
            float2 y0 = cadd(b0, t2), y1 = csub(b0, t2);
            float2 y2 = cadd(t1, t3), y3 = cmuli(csub(t1, t3));
            s[PADI(i0)]         = cadd(y0, y2);
            s[PADI(i0 + H)]     = cadd(y1, y3);
            s[PADI(i0 + 2 * H)] = csub(y0, y2);
            s[PADI(i0 + 3 * H)] = csub(y1, y3);
        }
        __syncthreads();
    }
    #pragma unroll
    for (int it = 0; it < QB / T_FFT; ++it) {
        int q = tid + it * T_FFT;
        float2 w1 = cconj(twid(tC, tF, q));
        float2 w2 = cconj(twid(tC, tF, 2 * q));
        float2 w3 = cconj(twid(tC, tF, 3 * q));
        float2 b0 = s[PADI(q)];
        float2 t1 = cmul(s[PADI(q + 4096)], w1);
        float2 t2 = cmul(s[PADI(q + 8192)], w2);
        float2 t3 = cmul(s[PADI(q + 12288)], w3);
        float2 y0 = cadd(b0, t2), y1 = csub(b0, t2);
        float2 y2 = cadd(t1, t3), y3 = cmuli(csub(t1, t3));
        float2 z0 = cadd(y0, y2);
        float2 z1 = cadd(y1, y3);
        float2 u0 = gu[q], u1 = gu[q + 4096];
        gout[q]        = make_float2(z0.x + Dv * u0.x, z0.y + Dv * u0.y);
        gout[q + 4096] = make_float2(z1.x + Dv * u1.x, z1.y + Dv * u1.y);
    }
}

// ------- kernel 1: twiddles + steps + fp32 Gauss-Jordan inverse of M --------
__global__ __launch_bounds__(256) void k_disc(const float* __restrict__ A,
                                              const float* __restrict__ logstep) {
    __shared__ float aug[64 * 132];   // [M | I], padded width
    __shared__ float fcol[64];
    __shared__ float sinv;
    const int tid = threadIdx.x;

    if (tid < 128) {
        const double PI = 3.14159265358979323846;
        double sv, cv, ang;
        ang = -2.0 * PI * (double)tid / 128.0;    sincos(ang, &sv, &cv);
        g_twC[tid] = make_float2((float)cv, (float)sv);
        ang = -2.0 * PI * (double)tid / 16384.0;  sincos(ang, &sv, &cv);
        g_twF[tid] = make_float2((float)cv, (float)sv);
        ang = -2.0 * PI * (double)tid / 256.0;    sincos(ang, &sv, &cv);
        g_twCN[tid] = make_float2((float)cv, (float)sv);
        ang = -2.0 * PI * (double)tid / 32768.0;  sincos(ang, &sv, &cv);
        g_twFN[tid] = make_float2((float)cv, (float)sv);
    }
    if (tid == 0) {
        float stf = (float)exp((double)logstep[0]);  // match ref's fp32 step
        g_stepD[0] = 0.5 * (double)stf;
        g_stepD[1] = (double)stf;
    }
    __syncthreads();
    const float hs = (float)g_stepD[0];

    for (int idx = tid; idx < 64 * 128; idx += 256) {
        int r = idx >> 7, c = idx & 127;
        float v;
        if (c < 64) v = (r == c ? 1.f : 0.f) - hs * A[r * 64 + c];
        else        v = (r == (c - 64)) ? 1.f : 0.f;
        aug[r * 132 + c] = v;
    }
    __syncthreads();

    const int gr  = tid >> 2;
    const int gc0 = tid & 3;
    for (int col = 0; col < 64; ++col) {
        if (tid == 0) sinv = 1.0f / aug[col * 132 + col];
        __syncthreads();
        float inv = sinv;
        for (int c = tid; c < 128; c += 256) aug[col * 132 + c] *= inv;
        if (tid < 64) fcol[tid] = (tid == col) ? 0.f : aug[tid * 132 + col];
        __syncthreads();
        float f = fcol[gr];
        for (int c = gc0; c < 128; c += 4)
            aug[gr * 132 + c] -= f * aug[col * 132 + c];
        __syncthreads();
    }

    for (int idx = tid; idx < 4096; idx += 256) {
        int r = idx >> 6, c = idx & 63;
        g_X0[idx] = aug[r * 132 + 64 + c];
    }
}

// ------- grid barrier (64-block single wave; counter pre-zeroed) ------------
__device__ __forceinline__ void grid_bar(unsigned phase) {
    __syncthreads();
    if (threadIdx.x == 0) {
        __threadfence();
        atomicAdd(&g_bar, 1u);
        const unsigned target = phase * 64u;
        while (atomicAdd(&g_bar, 0u) < target) { }
    }
    __syncthreads();
}

// ------- kernel 2: persistent — Newton refine + 9 df squarings --------------
// 64 blocks x 64 threads, one wave (R8-proven shell; df math replaces fp64).
__global__ __launch_bounds__(64) void k_power(const float* __restrict__ A,
                                              const float* __restrict__ B) {
    extern __shared__ char pmem[];
    float* X0s = reinterpret_cast<float*>(pmem);          // 16 KB (phases A/B)
    float* SH  = reinterpret_cast<float*>(pmem);          // 16 KB hi (squarings)
    float* SL  = reinterpret_cast<float*>(pmem) + 4096;   // 16 KB lo
    __shared__ float2 red[64];
    const int r = blockIdx.x, c = threadIdx.x;
    unsigned phase = 0;

    for (int i = c; i < 4096; i += 64) X0s[i] = g_X0[i];
    __syncthreads();
    const float  hs = (float)g_stepD[0];
    const double st = g_stepD[1];

    // phase A: R = I - M*X0 (row r), df; M = I - hs*A
    {
        float2 acc = make_float2(0.f, 0.f);
        for (int k = 0; k < 64; ++k) {
            float a = A[r * 64 + k];
            float p = __fmul_rn(hs, a);
            float e = fmaf(hs, a, -p);
            float2 m = df_two_sum((r == k ? 1.f : 0.f), -p);   // exact delta - p
            m.y = __fadd_rn(m.y, -e);                          // - exact product tail
            acc = df_add(acc, df_mul_f(m, X0s[k * 64 + c]));
        }
        float2 res = df_add(make_float2((r == c ? 1.f : 0.f), 0.f),
                            make_float2(-acc.x, -acc.y));
        g_RF[r * 64 + c] = __fadd_rn(res.x, res.y);
    }
    grid_bar(++phase);

    // phase B: X1 = X0 + X0*R ; Ab = 2*X1 - I (df) ; Bb = st * X1 * B
    {
        float corr = 0.f;
        for (int k = 0; k < 64; ++k)
            corr = fmaf(X0s[r * 64 + k], __ldcg(&g_RF[k * 64 + c]), corr);
        float2 x1 = df_two_sum(X0s[r * 64 + c], corr);
        float2 ab = df_add(df_add(x1, x1),
                           make_float2((r == c ? -1.f : 0.f), 0.f));
        __stcg(&g_DH0[r * 64 + c], ab.x);
        __stcg(&g_DL0[r * 64 + c], ab.y);
        g_AbF[r * 64 + c] = __fadd_rn(ab.x, ab.y);
        red[c] = df_mul_f(x1, B[c]);
        __syncthreads();
        if (c == 0) {
            float2 s = make_float2(0.f, 0.f);
            for (int i = 0; i < 64; ++i) s = df_add(s, red[i]);
            g_BbF[r] = (float)(st * ((double)s.x + (double)s.y));
        }
    }
    grid_bar(++phase);   // also fences smem aliasing X0s -> SH/SL

    // phases C1..C9: 9 df squarings; t=7 emits M128T, t=9 emits M512T
    for (int t = 1; t <= 9; ++t) {
        const float* srcH = (t & 1) ? g_DH0 : g_DH1;
        const float* srcL = (t & 1) ? g_DL0 : g_DL1;
        float*       dstH = (t & 1) ? g_DH1 : g_DH0;
        float*       dstL = (t & 1) ? g_DL1 : g_DL0;
        {
            const float4* sH4 = reinterpret_cast<const float4*>(srcH);
            const float4* sL4 = reinterpret_cast<const float4*>(srcL);
            float4* dH4 = reinterpret_cast<float4*>(SH);
            float4* dL4 = reinterpret_cast<float4*>(SL);
            for (int i = c; i < 1024; i += 64) {
                dH4[i] = __ldcg(&sH4[i]);
                dL4[i] = __ldcg(&sL4[i]);
            }
        }
        __syncthreads();
        float2 acc = make_float2(0.f, 0.f);
        #pragma unroll 4
        for (int q = 0; q < 64; ++q) {
            float2 a = make_float2(SH[r * 64 + q], SL[r * 64 + q]);
            float2 b = make_float2(SH[q * 64 + c], SL[q * 64 + c]);
            acc = df_add(acc, df_mul(a, b));
        }
        __stcg(&dstH[r * 64 + c], acc.x);
        __stcg(&dstL[r * 64 + c], acc.y);
        if (t == 7) g_M128T[c * 64 + r] = __fadd_rn(acc.x, acc.y);
        else if (t == 9) g_M512T[c * 64 + r] = __fadd_rn(acc.x, acc.y);
        if (t < 9) grid_bar(++phase);
        else __syncthreads();
    }
}

// ------- kernel 3: W serial chain || V seeds + 4 chains, then K (one block) -
#define CH_SMEM_BYTES 66048   // max(chains layout 13184, K layout 16512) floats * 4
__global__ __launch_bounds__(320) void k_chains(const float* __restrict__ C) {
    extern __shared__ float sm[];
    float* AbS   = sm;
    float* M128S = sm + 4096;
    float* M512S = sm + 8192;
    float* wbuf  = sm + 12288;          // [2][64]
    float* vseed = sm + 12416;          // [4][64]
    float* vbuf  = sm + 12672;          // [4][2][64]
    const int tid = threadIdx.x;

    for (int i = tid; i < 4096; i += 320) AbS[i]   = g_AbF[i];
    for (int i = tid; i < 4096; i += 320) M128S[i] = g_M128T[i];
    for (int i = tid; i < 4096; i += 320) M512S[i] = g_M512T[i];
    __syncthreads();

    if (tid < 64) {
        // ---- W chain: W[0]=C, W[j] = W[j-1] * Ab ----
        const int c = tid;
        float w = C[c];
        wbuf[c] = w;
        g_W[c] = w;
        asm volatile("bar.sync 2, 64;" ::: "memory");
        int p = 0;
        for (int stp = 1; stp < 128; ++stp) {
            const float* wr = wbuf + p * 64;
            float a0 = 0.f, a1 = 0.f, a2 = 0.f, a3 = 0.f;
            #pragma unroll 16
            for (int r = 0; r < 64; r += 4) {
                a0 += wr[r + 0] * AbS[(r + 0) * 64 + c];
                a1 += wr[r + 1] * AbS[(r + 1) * 64 + c];
                a2 += wr[r + 2] * AbS[(r + 2) * 64 + c];
                a3 += wr[r + 3] * AbS[(r + 3) * 64 + c];
            }
            float nw = (a0 + a1) + (a2 + a3);
            wbuf[(1 - p) * 64 + c] = nw;
            g_W[stp * 64 + c] = nw;
            p ^= 1;
            asm volatile("bar.sync 2, 64;" ::: "memory");
        }
    } else {
        // ---- V: seeds V[0..3] via M128, then 4 chains stepped by M512 ----
        const int t = tid - 64;
        if (t < 64) {
            float v = g_BbF[t];
            vseed[t] = v;
            g_V[t] = v;
        }
        asm volatile("bar.sync 3, 256;" ::: "memory");
        for (int sd = 1; sd <= 3; ++sd) {
            float acc = 0.f;
            if (t < 64) {
                const float* vp = vseed + (sd - 1) * 64;
                float a0 = 0.f, a1 = 0.f, a2 = 0.f, a3 = 0.f;
                #pragma unroll 16
                for (int cc = 0; cc < 64; cc += 4) {
                    a0 += M128S[(cc + 0) * 64 + t] * vp[cc + 0];
                    a1 += M128S[(cc + 1) * 64 + t] * vp[cc + 1];
                    a2 += M128S[(cc + 2) * 64 + t] * vp[cc + 2];
                    a3 += M128S[(cc + 3) * 64 + t] * vp[cc + 3];
                }
                acc = (a0 + a1) + (a2 + a3);
            }
            asm volatile("bar.sync 3, 256;" ::: "memory");
            if (t < 64) {
                vseed[sd * 64 + t] = acc;
                g_V[sd * 64 + t] = acc;
            }
            asm volatile("bar.sync 3, 256;" ::: "memory");
        }
        const int ch = t >> 6, r = t & 63;
        vbuf[ch * 128 + r] = vseed[ch * 64 + r];
        asm volatile("bar.sync 3, 256;" ::: "memory");
        int p = 0;
        for (int sp = 1; sp <= 31; ++sp) {
            const float* vp = vbuf + ch * 128 + p * 64;
            float a0 = 0.f, a1 = 0.f, a2 = 0.f, a3 = 0.f;
            #pragma unroll 16
            for (int cc = 0; cc < 64; cc += 4) {
                a0 += M512S[(cc + 0) * 64 + r] * vp[cc + 0];
                a1 += M512S[(cc + 1) * 64 + r] * vp[cc + 1];
                a2 += M512S[(cc + 2) * 64 + r] * vp[cc + 2];
                a3 += M512S[(cc + 3) * 64 + r] * vp[cc + 3];
            }
            float acc = (a0 + a1) + (a2 + a3);
            vbuf[ch * 128 + (1 - p) * 64 + r] = acc;
            g_V[(ch + 4 * sp) * 64 + r] = acc;
            p ^= 1;
            asm volatile("bar.sync 3, 256;" ::: "memory");
        }
    }

    // ---- K phase: K[128 i + j] = W[j] . V[i] (smem-staged, padded W) ----
    __syncthreads();
    {
        float* Wp = sm;           // 128 rows * 65 stride = 8320 floats
        float* Vp = sm + 8320;    // 8192 floats
        for (int idx = tid; idx < 8192; idx += 320) {
            Wp[(idx >> 6) * 65 + (idx & 63)] = g_W[idx];
            Vp[idx] = g_V[idx];
        }
        __syncthreads();
        if (tid < 256) {
            const int j = tid & 127;
            const int g = tid >> 7;           // 0 or 1
            const float* wr = Wp + j * 65;
            for (int i = g; i < 128; i += 2) {
                const float* vr = Vp + i * 64;
                float a0 = 0.f, a1 = 0.f, a2 = 0.f, a3 = 0.f;
                #pragma unroll 16
                for (int rr = 0; rr < 64; rr += 4) {
                    a0 = fmaf(wr[rr + 0], vr[rr + 0], a0);
                    a1 = fmaf(wr[rr + 1], vr[rr + 1], a1);
                    a2 = fmaf(wr[rr + 2], vr[rr + 2], a2);
                    a3 = fmaf(wr[rr + 3], vr[rr + 3], a3);
                }
                g_K[i * 128 + j] = (a0 + a1) + (a2 + a3);
            }
        }
    }
}

// ---------------- kernel 4: H = rfft(K, 32768) / MF -------------------------
__global__ __launch_bounds__(T_FFT) void k_kfft() {
    extern __shared__ float2 sh2[];
    float2* s   = sh2;
    float2* tC  = s + 17408;
    float2* tF  = tC + 128;
    float2* tCN = tF + 128;
    float2* tFN = tCN + 128;
    const int tid = threadIdx.x;
    if (tid < 128) {
        tC[tid] = g_twC[tid]; tF[tid] = g_twF[tid];
        tCN[tid] = g_twCN[tid]; tFN[tid] = g_twFN[tid];
    }
    __syncthreads();
    fft_fwd(s, tC, tF, reinterpret_cast<const float2*>(g_K));

    const float sc = 1.0f / (float)MF;
    if (tid == 0) {
        float2 Z0 = s[PADI(0)];
        g_H[0]  = make_float2((Z0.x + Z0.y) * sc, 0.f);
        g_H[MF] = make_float2((Z0.x - Z0.y) * sc, 0.f);
    }
    for (int k = tid + 1; k <= HALF; k += T_FFT) {
        int rk = PADI(rev4_14(k));
        int rm = PADI(rev4_14(MF - k));
        float2 a  = s[rk];
        float2 bb = cconj(s[rm]);
        float2 E  = make_float2(0.5f * (a.x + bb.x), 0.5f * (a.y + bb.y));
        float2 Od = make_float2(0.5f * (a.x - bb.x), 0.5f * (a.y - bb.y));
        float2 wN = cmul(tCN[k >> 7], tFN[k & 127]);
        float2 g  = make_float2(wN.y, -wN.x);
        float2 gOd = cmul(g, Od);
        g_H[k]      = make_float2((E.x + gOd.x) * sc, (E.y + gOd.y) * sc);
        g_H[MF - k] = make_float2((E.x - gOd.x) * sc, -(E.y - gOd.y) * sc);
    }
}

// ---------------- kernel 5: per-row FFT conv + D*u --------------------------
__global__ __launch_bounds__(T_FFT) void k_conv(const float* __restrict__ u,
                                                const float* __restrict__ Dp,
                                                float* __restrict__ out) {
    extern __shared__ float2 sh2[];
    float2* s   = sh2;
    float2* tC  = s + 17408;
    float2* tF  = tC + 128;
    float2* tCN = tF + 128;
    float2* tFN = tCN + 128;
    const int tid = threadIdx.x;
    const int b = blockIdx.x;
    if (tid < 128) {
        tC[tid] = g_twC[tid]; tF[tid] = g_twF[tid];
        tCN[tid] = g_twCN[tid]; tFN[tid] = g_twFN[tid];
    }
    __syncthreads();

    const float2* u2 = reinterpret_cast<const float2*>(u) + (size_t)b * HALF;
    fft_fwd(s, tC, tF, u2);

    if (tid == 0) {
        float2 Z0 = s[PADI(0)];
        float X0 = Z0.x + Z0.y;
        float XM = Z0.x - Z0.y;
        float Y0 = X0 * g_H[0].x;
        float YM = XM * g_H[MF].x;
        s[PADI(0)] = make_float2(0.5f * (Y0 + YM), 0.5f * (Y0 - YM));
    }
    for (int k = tid + 1; k <= HALF; k += T_FFT) {
        int rk = PADI(rev4_14(k));
        int rm = PADI(rev4_14(MF - k));
        float2 a  = s[rk];
        float2 bb = cconj(s[rm]);
        float2 E  = make_float2(0.5f * (a.x + bb.x), 0.5f * (a.y + bb.y));
        float2 Od = make_float2(0.5f * (a.x - bb.x), 0.5f * (a.y - bb.y));
        float2 wN = cmul(tCN[k >> 7], tFN[k & 127]);
        float2 g  = make_float2(wN.y, -wN.x);
        float2 gOd = cmul(g, Od);
        float2 Xk = make_float2(E.x + gOd.x, E.y + gOd.y);
        float2 Xm = make_float2(E.x - gOd.x, -(E.y - gOd.y));
        float2 Yk = cmul(Xk, g_H[k]);
        float2 Ym = cmul(Xm, g_H[MF - k]);
        float2 cYm = cconj(Ym);
        float2 Ep  = make_float2(0.5f * (Yk.x + cYm.x), 0.5f * (Yk.y + cYm.y));
        float2 Dd  = make_float2(0.5f * (Yk.x - cYm.x), 0.5f * (Yk.y - cYm.y));
        float2 t1 = cmul(cconj(g), Dd);
        float2 t2 = cmul(g, cconj(Dd));
        s[rk] = make_float2(Ep.x + t1.x, Ep.y + t1.y);
        s[rm] = make_float2(Ep.x - t2.x, -Ep.y - t2.y);
    }
    __syncthreads();

    const float Dv = Dp[0];
    float2* o2 = reinterpret_cast<float2*>(out) + (size_t)b * HALF;
    fft_inv(s, tC, tF, o2, u2, Dv);
}

// ---------------- launch ----------------------------------------------------
extern "C" void kernel_launch(void* const* d_in, const int* in_sizes, int n_in,
                              void* d_out, int out_size) {
    const float* u  = (const float*)d_in[0];
    const float* A  = (const float*)d_in[1];
    const float* B  = (const float*)d_in[2];
    const float* C  = (const float*)d_in[3];
    const float* D  = (const float*)d_in[4];
    const float* ls = (const float*)d_in[5];
    float* out = (float*)d_out;

    const int smemFFT = (17408 + 4 * 128) * (int)sizeof(float2);   // 143360
    const int smemPw  = 8192 * (int)sizeof(float);                 // 32768

    cudaFuncSetAttribute(k_chains, cudaFuncAttributeMaxDynamicSharedMemorySize, CH_SMEM_BYTES);
    cudaFuncSetAttribute(k_kfft, cudaFuncAttributeMaxDynamicSharedMemorySize, smemFFT);
    cudaFuncSetAttribute(k_conv, cudaFuncAttributeMaxDynamicSharedMemorySize, smemFFT);

    void* barp = nullptr;
    cudaGetSymbolAddress(&barp, g_bar);
    cudaMemsetAsync(barp, 0, sizeof(unsigned));

    k_disc<<<1, 256>>>(A, ls);
    k_power<<<64, 64, smemPw>>>(A, B);
    k_chains<<<1, 320, CH_SMEM_BYTES>>>(C);
    k_kfft<<<1, T_FFT, smemFFT>>>();
    k_conv<<<512, T_FFT, smemFFT>>>(u, D, out);
}

// round 14
// speedup vs baseline: 2.9381x; 1.0368x over previous
#include <cuda_runtime.h>
#include <math.h>

#define T_FFT 512
#define LOG2M 14
#define MF    16384      // complex FFT length (real length N = 32768)
#define HALF  8192       // MF/2
#define LSEQ  16384
#define QB    4096       // MF/4 butterflies per radix-4 stage
#define PADI(i) ((i) + ((i) >> 4))

// ---------------- device scratch ----------------
__device__ float  g_W[128 * 64];
__device__ float  g_V[128 * 64];
__device__ float  g_K[LSEQ];
__device__ float2 g_H[MF + 1];
__device__ float2 g_twC[128];   // e^{-2pi i h/128}
__device__ float2 g_twF[128];   // e^{-2pi i l/16384}
__device__ float2 g_twCN[128];  // e^{-2pi i h/256}
__device__ float2 g_twFN[128];  // e^{-2pi i l/32768}

__device__ float  g_X0[4096];
__device__ float  g_RF[4096];                 // fp32 Newton residual
__device__ float  g_DH0[4096], g_DL0[4096];   // df ping-pong (hi, lo)
__device__ float  g_DH1[4096], g_DL1[4096];
__device__ float  g_AbF[4096];
__device__ float  g_PW[7][4096];   // fp32 Ab^(2^t); [0] unused (g_AbF)
__device__ float  g_M128T[4096];
__device__ float  g_M512T[4096];
__device__ float  g_BbF[64];
__device__ double g_stepD[2];   // hs, st
__device__ unsigned g_bar;      // grid-barrier counter (memset to 0 pre-launch)

__device__ __forceinline__ float2 cmul(float2 a, float2 b) {
    return make_float2(a.x * b.x - a.y * b.y, a.x * b.y + a.y * b.x);
}
__device__ __forceinline__ float2 cconj(float2 a) { return make_float2(a.x, -a.y); }
__device__ __forceinline__ float2 cadd(float2 a, float2 b) { return make_float2(a.x + b.x, a.y + b.y); }
__device__ __forceinline__ float2 csub(float2 a, float2 b) { return make_float2(a.x - b.x, a.y - b.y); }
__device__ __forceinline__ float2 cmulni(float2 a) { return make_float2(a.y, -a.x); }  // -i*a
__device__ __forceinline__ float2 cmuli(float2 a)  { return make_float2(-a.y, a.x); }  // +i*a

__device__ __forceinline__ float2 twid(const float2* tC, const float2* tF, int x) {
    return cmul(tC[x >> 7], tF[x & 127]);   // e^{-2pi i x / 16384}, x < 16384
}

__device__ __forceinline__ int rev4_14(int k) {
    unsigned br = __brev((unsigned)k) >> 18;
    return (int)(((br & 0x2AAAu) >> 1) | ((br & 0x1555u) << 1));
}

__constant__ float2 c_w16a[4] = {
    {1.0f, 0.0f}, {0.92387953251f, -0.38268343236f},
    {0.70710678119f, -0.70710678119f}, {0.38268343236f, -0.92387953251f}};
__constant__ float2 c_w16b[4] = {
    {1.0f, 0.0f}, {0.70710678119f, -0.70710678119f},
    {0.0f, -1.0f}, {-0.70710678119f, -0.70710678119f}};
__constant__ float2 c_w16c[4] = {
    {1.0f, 0.0f}, {0.38268343236f, -0.92387953251f},
    {-0.70710678119f, -0.70710678119f}, {-0.92387953251f, 0.38268343236f}};

// ---------------- double-float (2x fp32) helpers ----------------
__device__ __forceinline__ float2 df_two_sum(float a, float b) {
    float s  = __fadd_rn(a, b);
    float bb = __fsub_rn(s, a);
    float e  = __fadd_rn(__fsub_rn(a, __fsub_rn(s, bb)), __fsub_rn(b, bb));
    return make_float2(s, e);
}
__device__ __forceinline__ float2 df_mul(float2 a, float2 b) {
    float p = __fmul_rn(a.x, b.x);
    float e = fmaf(a.x, b.x, -p);
    e = __fadd_rn(e, __fadd_rn(__fmul_rn(a.x, b.y), __fmul_rn(a.y, b.x)));
    return df_two_sum(p, e);
}
__device__ __forceinline__ float2 df_mul_f(float2 a, float b) {
    float p = __fmul_rn(a.x, b);
    float e = fmaf(a.x, b, -p);
    e = __fadd_rn(e, __fmul_rn(a.y, b));
    return df_two_sum(p, e);
}
__device__ __forceinline__ float2 df_add(float2 a, float2 b) {
    float2 s = df_two_sum(a.x, b.x);
    float e  = __fadd_rn(s.y, __fadd_rn(a.y, b.y));
    return df_two_sum(s.x, e);
}

// ---------- forward FFT: fused global-load first stage (upper half zero) ----
__device__ void fft_fwd(float2* s, const float2* tC, const float2* tF,
                        const float2* __restrict__ gin) {
    const int tid = threadIdx.x;
    #pragma unroll
    for (int it = 0; it < QB / T_FFT; ++it) {
        int q = tid + it * T_FFT;
        float2 a = gin[q];
        float2 b = gin[q + 4096];
        float2 w1 = twid(tC, tF, q);
        float2 w2 = twid(tC, tF, 2 * q);
        float2 w3 = twid(tC, tF, 3 * q);
        s[PADI(q)]         = cadd(a, b);
        s[PADI(q + 4096)]  = cmul(cadd(a, cmulni(b)), w1);
        s[PADI(q + 8192)]  = cmul(csub(a, b), w2);
        s[PADI(q + 12288)] = cmul(cadd(a, cmuli(b)), w3);
    }
    __syncthreads();
    #pragma unroll
    for (int st = 0; st < 4; ++st) {
        const int lg = 10 - 2 * st;
        const int H = 1 << lg;
        #pragma unroll
        for (int it = 0; it < QB / T_FFT; ++it) {
            int q = tid + it * T_FFT;
            int j = q & (H - 1);
            int i0 = ((q >> lg) << (lg + 2)) + j;
            float2 a = s[PADI(i0)], b = s[PADI(i0 + H)];
            float2 c = s[PADI(i0 + 2 * H)], d = s[PADI(i0 + 3 * H)];
            float2 y0 = cadd(a, c), y1 = csub(a, c);
            float2 y2 = cadd(b, d), y3 = csub(b, d);
            int x = j << (12 - lg);
            float2 w1 = twid(tC, tF, x);
            float2 w2 = twid(tC, tF, 2 * x);
            float2 w3 = twid(tC, tF, 3 * x);
            float2 m3 = cmulni(y3);
            s[PADI(i0)]         = cadd(y0, y2);
            s[PADI(i0 + H)]     = cmul(cadd(y1, m3), w1);
            s[PADI(i0 + 2 * H)] = cmul(csub(y0, y2), w2);
            s[PADI(i0 + 3 * H)] = cmul(csub(y1, m3), w3);
        }
        __syncthreads();
    }
    #pragma unroll
    for (int it = 0; it < (MF / 16) / T_FFT; ++it) {
        int m = tid + it * T_FFT;
        int base = 16 * m;
        float2 v[16];
        #pragma unroll
        for (int e = 0; e < 16; ++e) v[e] = s[PADI(base + e)];
        #pragma unroll
        for (int j = 0; j < 4; ++j) {
            float2 a = v[j], b = v[j + 4], c = v[j + 8], d = v[j + 12];
            float2 y0 = cadd(a, c), y1 = csub(a, c);
            float2 y2 = cadd(b, d), y3 = csub(b, d);
            float2 m3 = cmulni(y3);
            v[j]      = cadd(y0, y2);
            v[j + 4]  = cmul(cadd(y1, m3), c_w16a[j]);
            v[j + 8]  = cmul(csub(y0, y2), c_w16b[j]);
            v[j + 12] = cmul(csub(y1, m3), c_w16c[j]);
        }
        #pragma unroll
        for (int g = 0; g < 4; ++g) {
            float2 a = v[4 * g], b = v[4 * g + 1], c = v[4 * g + 2], d = v[4 * g + 3];
            float2 y0 = cadd(a, c), y1 = csub(a, c);
            float2 y2 = cadd(b, d), y3 = csub(b, d);
            float2 m3 = cmulni(y3);
            v[4 * g]     = cadd(y0, y2);
            v[4 * g + 1] = cadd(y1, m3);
            v[4 * g + 2] = csub(y0, y2);
            v[4 * g + 3] = csub(y1, m3);
        }
        #pragma unroll
        for (int e = 0; e < 16; ++e) s[PADI(base + e)] = v[e];
    }
    __syncthreads();
}

// ---------- inverse FFT: fused last stage writes z + D*u directly to gmem ---
__device__ void fft_inv(float2* s, const float2* tC, const float2* tF,
                        float2* __restrict__ gout, const float2* __restrict__ gu,
                        float Dv) {
    const int tid = threadIdx.x;
    #pragma unroll
    for (int it = 0; it < (MF / 16) / T_FFT; ++it) {
        int m = tid + it * T_FFT;
        int base = 16 * m;
        float2 v[16];
        #pragma unroll
        for (int e = 0; e < 16; ++e) v[e] = s[PADI(base + e)];
        #pragma unroll
        for (int g = 0; g < 4; ++g) {
            float2 b0 = v[4 * g], b1 = v[4 * g + 1], b2 = v[4 * g + 2], b3 = v[4 * g + 3];
            float2 y0 = cadd(b0, b2), y1 = csub(b0, b2);
            float2 y2 = cadd(b1, b3), y3 = cmuli(csub(b1, b3));
            v[4 * g]     = cadd(y0, y2);
            v[4 * g + 1] = cadd(y1, y3);
            v[4 * g + 2] = csub(y0, y2);
            v[4 * g + 3] = csub(y1, y3);
        }
        #pragma unroll
        for (int j = 0; j < 4; ++j) {
            float2 b0 = v[j];
            float2 t1 = cmul(v[j + 4],  cconj(c_w16a[j]));
            float2 t2 = cmul(v[j + 8],  cconj(c_w16b[j]));
            float2 t3 = cmul(v[j + 12], cconj(c_w16c[j]));
            float2 y0 = cadd(b0, t2), y1 = csub(b0, t2);
            float2 y2 = cadd(t1, t3), y3 = cmuli(csub(t1, t3));
            v[j]      = cadd(y0, y2);
            v[j + 4]  = cadd(y1, y3);
            v[j + 8]  = csub(y0, y2);
            v[j + 12] = csub(y1, y3);
        }
        #pragma unroll
        for (int e = 0; e < 16; ++e) s[PADI(base + e)] = v[e];
    }
    __syncthreads();
    #pragma unroll
    for (int st = 0; st < 4; ++st) {
        const int lg = 4 + 2 * st;
        const int H = 1 << lg;
        #pragma unroll
        for (int it = 0; it < QB / T_FFT; ++it) {
            int q = tid + it * T_FFT;
            int j = q & (H - 1);
            int i0 = ((q >> lg) << (lg + 2)) + j;
            int x = j << (12 - lg);
            float2 w1 = cconj(twid(tC, tF, x));
            float2 w2 = cconj(twid(tC, tF, 2 * x));
            float2 w3 = cconj(twid(tC, tF, 3 * x));
            float2 b0 = s[PADI(i0)];
            float2 t1 = cmul(s[PADI(i0 + H)], w1);
            float2 t2 = cmul(s[PADI(i0 + 2 * H)], w2);
            float2 t3 = cmul(s[PADI(i0 + 3 * H)], w3);
            float2 y0 = cadd(b0, t2), y1 = csub(b0, t2);
            float2 y2 = cadd(t1, t3), y3 = cmuli(csub(t1, t3));
            s[PADI(i0)]         = cadd(y0, y2);
            s[PADI(i0 + H)]     = cadd(y1, y3);
            s[PADI(i0 + 2 * H)] = csub(y0, y2);
            s[PADI(i0 + 3 * H)] = csub(y1, y3);
        }
        __syncthreads();
    }
    #pragma unroll
    for (int it = 0; it < QB / T_FFT; ++it) {
        int q = tid + it * T_FFT;
        float2 w1 = cconj(twid(tC, tF, q));
        float2 w2 = cconj(twid(tC, tF, 2 * q));
        float2 w3 = cconj(twid(tC, tF, 3 * q));
        float2 b0 = s[PADI(q)];
        float2 t1 = cmul(s[PADI(q + 4096)], w1);
        float2 t2 = cmul(s[PADI(q + 8192)], w2);
        float2 t3 = cmul(s[PADI(q + 12288)], w3);
        float2 y0 = cadd(b0, t2), y1 = csub(b0, t2);
        float2 y2 = cadd(t1, t3), y3 = cmuli(csub(t1, t3));
        float2 z0 = cadd(y0, y2);
        float2 z1 = cadd(y1, y3);
        float2 u0 = gu[q], u1 = gu[q + 4096];
        gout[q]        = make_float2(z0.x + Dv * u0.x, z0.y + Dv * u0.y);
        gout[q + 4096] = make_float2(z1.x + Dv * u1.x, z1.y + Dv * u1.y);
    }
}

// ------- kernel 1: twiddles + steps + fp32 Gauss-Jordan inverse of M --------
__global__ __launch_bounds__(256) void k_disc(const float* __restrict__ A,
                                              const float* __restrict__ logstep) {
    __shared__ float aug[64 * 132];   // [M | I], padded width
    __shared__ float fcol[64];
    __shared__ float sinv;
    const int tid = threadIdx.x;

    if (tid < 128) {
        const double PI = 3.14159265358979323846;
        double sv, cv, ang;
        ang = -2.0 * PI * (double)tid / 128.0;    sincos(ang, &sv, &cv);
        g_twC[tid] = make_float2((float)cv, (float)sv);
        ang = -2.0 * PI * (double)tid / 16384.0;  sincos(ang, &sv, &cv);
        g_twF[tid] = make_float2((float)cv, (float)sv);
        ang = -2.0 * PI * (double)tid / 256.0;    sincos(ang, &sv, &cv);
        g_twCN[tid] = make_float2((float)cv, (float)sv);
        ang = -2.0 * PI * (double)tid / 32768.0;  sincos(ang, &sv, &cv);
        g_twFN[tid] = make_float2((float)cv, (float)sv);
    }
    if (tid == 0) {
        float stf = (float)exp((double)logstep[0]);  // match ref's fp32 step
        g_stepD[0] = 0.5 * (double)stf;
        g_stepD[1] = (double)stf;
    }
    __syncthreads();
    const float hs = (float)g_stepD[0];

    for (int idx = tid; idx < 64 * 128; idx += 256) {
        int r = idx >> 7, c = idx & 127;
        float v;
        if (c < 64) v = (r == c ? 1.f : 0.f) - hs * A[r * 64 + c];
        else        v = (r == (c - 64)) ? 1.f : 0.f;
        aug[r * 132 + c] = v;
    }
    __syncthreads();

    const int gr  = tid >> 2;
    const int gc0 = tid & 3;
    for (int col = 0; col < 64; ++col) {
        if (tid == 0) sinv = 1.0f / aug[col * 132 + col];
        __syncthreads();
        float inv = sinv;
        for (int c = tid; c < 128; c += 256) aug[col * 132 + c] *= inv;
        if (tid < 64) fcol[tid] = (tid == col) ? 0.f : aug[tid * 132 + col];
        __syncthreads();
        float f = fcol[gr];
        for (int c = gc0; c < 128; c += 4)
            aug[gr * 132 + c] -= f * aug[col * 132 + c];
        __syncthreads();
    }

    for (int idx = tid; idx < 4096; idx += 256) {
        int r = idx >> 6, c = idx & 63;
        g_X0[idx] = aug[r * 132 + 64 + c];
    }
}

// ------- grid barrier (64-block single wave; counter pre-zeroed) ------------
__device__ __forceinline__ void grid_bar(unsigned phase) {
    __syncthreads();
    if (threadIdx.x == 0) {
        __threadfence();
        atomicAdd(&g_bar, 1u);
        const unsigned target = phase * 64u;
        while (atomicAdd(&g_bar, 0u) < target) { }
    }
    __syncthreads();
}

// ------- kernel 2: persistent — Newton refine + 9 df squarings --------------
// 64 blocks x 64 threads, one wave (R8/R12-proven shell).
__global__ __launch_bounds__(64) void k_power(const float* __restrict__ A,
                                              const float* __restrict__ B) {
    extern __shared__ char pmem[];
    float* X0s = reinterpret_cast<float*>(pmem);          // 16 KB (phases A/B)
    float* SH  = reinterpret_cast<float*>(pmem);          // 16 KB hi (squarings)
    float* SL  = reinterpret_cast<float*>(pmem) + 4096;   // 16 KB lo
    __shared__ float2 red[64];
    const int r = blockIdx.x, c = threadIdx.x;
    unsigned phase = 0;

    for (int i = c; i < 4096; i += 64) X0s[i] = g_X0[i];
    __syncthreads();
    const float  hs = (float)g_stepD[0];
    const double st = g_stepD[1];

    // phase A: R = I - M*X0 (row r), df; M = I - hs*A
    {
        float2 acc = make_float2(0.f, 0.f);
        for (int k = 0; k < 64; ++k) {
            float a = A[r * 64 + k];
            float p = __fmul_rn(hs, a);
            float e = fmaf(hs, a, -p);
            float2 m = df_two_sum((r == k ? 1.f : 0.f), -p);
            m.y = __fadd_rn(m.y, -e);
            acc = df_add(acc, df_mul_f(m, X0s[k * 64 + c]));
        }
        float2 res = df_add(make_float2((r == c ? 1.f : 0.f), 0.f),
                            make_float2(-acc.x, -acc.y));
        g_RF[r * 64 + c] = __fadd_rn(res.x, res.y);
    }
    grid_bar(++phase);

    // phase B: X1 = X0 + X0*R ; Ab = 2*X1 - I (df) ; Bb = st * X1 * B
    {
        float corr = 0.f;
        for (int k = 0; k < 64; ++k)
            corr = fmaf(X0s[r * 64 + k], __ldcg(&g_RF[k * 64 + c]), corr);
        float2 x1 = df_two_sum(X0s[r * 64 + c], corr);
        float2 ab = df_add(df_add(x1, x1),
                           make_float2((r == c ? -1.f : 0.f), 0.f));
        __stcg(&g_DH0[r * 64 + c], ab.x);
        __stcg(&g_DL0[r * 64 + c], ab.y);
        g_AbF[r * 64 + c] = __fadd_rn(ab.x, ab.y);
        red[c] = df_mul_f(x1, B[c]);
        __syncthreads();
        if (c == 0) {
            float2 s = make_float2(0.f, 0.f);
            for (int i = 0; i < 64; ++i) s = df_add(s, red[i]);
            g_BbF[r] = (float)(st * ((double)s.x + (double)s.y));
        }
    }
    grid_bar(++phase);   // also fences smem aliasing X0s -> SH/SL

    // phases C1..C9: 9 df squarings; t<=6 emits PW[t]; t=7 M128T, t=9 M512T
    for (int t = 1; t <= 9; ++t) {
        const float* srcH = (t & 1) ? g_DH0 : g_DH1;
        const float* srcL = (t & 1) ? g_DL0 : g_DL1;
        float*       dstH = (t & 1) ? g_DH1 : g_DH0;
        float*       dstL = (t & 1) ? g_DL1 : g_DL0;
        {
            const float4* sH4 = reinterpret_cast<const float4*>(srcH);
            const float4* sL4 = reinterpret_cast<const float4*>(srcL);
            float4* dH4 = reinterpret_cast<float4*>(SH);
            float4* dL4 = reinterpret_cast<float4*>(SL);
            for (int i = c; i < 1024; i += 64) {
                dH4[i] = __ldcg(&sH4[i]);
                dL4[i] = __ldcg(&sL4[i]);
            }
        }
        __syncthreads();
        float2 acc = make_float2(0.f, 0.f);
        #pragma unroll 4
        for (int q = 0; q < 64; ++q) {
            float2 a = make_float2(SH[r * 64 + q], SL[r * 64 + q]);
            float2 b = make_float2(SH[q * 64 + c], SL[q * 64 + c]);
            acc = df_add(acc, df_mul(a, b));
        }
        __stcg(&dstH[r * 64 + c], acc.x);
        __stcg(&dstL[r * 64 + c], acc.y);
        float f32 = __fadd_rn(acc.x, acc.y);
        if (t <= 6) g_PW[t][r * 64 + c] = f32;
        else if (t == 7) g_M128T[c * 64 + r] = f32;
        else if (t == 9) g_M512T[c * 64 + r] = f32;
        if (t < 9) grid_bar(++phase);
        else __syncthreads();
    }
}

// ------- kernel 3: W doubling + V chains + K + kfft (ONE block, 512 thr) ----
// smem: float M[4096] | WS[128*65] | VS[128*64]  (82 KB) ... then reused as
// FFT buffer (143 KB total allocation).
__global__ __launch_bounds__(512) void k_prep2(const float* __restrict__ C) {
    extern __shared__ char smc[];
    float* M  = reinterpret_cast<float*>(smc);            // 4096
    float* WS = reinterpret_cast<float*>(smc) + 4096;     // 128*65 = 8320
    float* VS = reinterpret_cast<float*>(smc) + 12416;    // 8192
    const int tid = threadIdx.x;

    // ---- W doubling: WS[0] = C; levels t=0..6: W[j+2^t] = W[j]*Ab^(2^t) ----
    if (tid < 64) WS[tid] = C[tid];
    __syncthreads();
    for (int t = 0; t < 7; ++t) {
        const float* src = (t == 0) ? g_AbF : g_PW[t];
        for (int i = tid; i < 4096; i += 512) M[i] = src[i];
        __syncthreads();
        const int rows = 1 << t;
        for (int jb = 0; jb < rows; jb += 8) {
            const int j = jb + (tid >> 6);
            const int c = tid & 63;
            float nw = 0.f;
            if (j < rows) {
                const float* wr = WS + j * 65;
                float a0 = 0.f, a1 = 0.f, a2 = 0.f, a3 = 0.f;
                #pragma unroll 16
                for (int r = 0; r < 64; r += 4) {
                    a0 = fmaf(wr[r + 0], M[(r + 0) * 64 + c], a0);
                    a1 = fmaf(wr[r + 1], M[(r + 1) * 64 + c], a1);
                    a2 = fmaf(wr[r + 2], M[(r + 2) * 64 + c], a2);
                    a3 = fmaf(wr[r + 3], M[(r + 3) * 64 + c], a3);
                }
                nw = (a0 + a1) + (a2 + a3);
            }
            __syncthreads();
            if (j < rows) WS[(j + rows) * 65 + c] = nw;
            __syncthreads();
        }
    }

    // ---- V: seeds 0..3 via M128T, then 4 chains stepped by M512T ----
    for (int i = tid; i < 4096; i += 512) M[i] = g_M128T[i];
    if (tid < 64) VS[tid] = g_BbF[tid];
    __syncthreads();
    for (int sd = 1; sd <= 3; ++sd) {
        float acc = 0.f;
        if (tid < 64) {
            const float* vp = VS + (sd - 1) * 64;
            float a0 = 0.f, a1 = 0.f, a2 = 0.f, a3 = 0.f;
            #pragma unroll 16
            for (int cc = 0; cc < 64; cc += 4) {
                a0 = fmaf(M[(cc + 0) * 64 + tid], vp[cc + 0], a0);
                a1 = fmaf(M[(cc + 1) * 64 + tid], vp[cc + 1], a1);
                a2 = fmaf(M[(cc + 2) * 64 + tid], vp[cc + 2], a2);
                a3 = fmaf(M[(cc + 3) * 64 + tid], vp[cc + 3], a3);
            }
            acc = (a0 + a1) + (a2 + a3);
        }
        __syncthreads();
        if (tid < 64) VS[sd * 64 + tid] = acc;
        __syncthreads();
    }
    for (int i = tid; i < 4096; i += 512) M[i] = g_M512T[i];
    __syncthreads();
    {
        const int ch = tid >> 6;        // 0..7 (only 0..3 active)
        const int r  = tid & 63;
        for (int sp = 1; sp <= 31; ++sp) {
            float acc = 0.f;
            if (ch < 4) {
                const float* vp = VS + (ch + 4 * (sp - 1)) * 64;
                float a0 = 0.f, a1 = 0.f, a2 = 0.f, a3 = 0.f;
                #pragma unroll 16
                for (int cc = 0; cc < 64; cc += 4) {
                    a0 = fmaf(M[(cc + 0) * 64 + r], vp[cc + 0], a0);
                    a1 = fmaf(M[(cc + 1) * 64 + r], vp[cc + 1], a1);
                    a2 = fmaf(M[(cc + 2) * 64 + r], vp[cc + 2], a2);
                    a3 = fmaf(M[(cc + 3) * 64 + r], vp[cc + 3], a3);
                }
                acc = (a0 + a1) + (a2 + a3);
            }
            __syncthreads();
            if (ch < 4) VS[(ch + 4 * sp) * 64 + r] = acc;
            __syncthreads();
        }
    }

    // ---- K: K[128 i + j] = WS[j] . VS[i] ----
    {
        const int j = tid & 127;
        const int g = tid >> 7;          // 0..3
        const float* wr = WS + j * 65;
        for (int i = g; i < 128; i += 4) {
            const float* vr = VS + i * 64;
            float a0 = 0.f, a1 = 0.f, a2 = 0.f, a3 = 0.f;
            #pragma unroll 16
            for (int rr = 0; rr < 64; rr += 4) {
                a0 = fmaf(wr[rr + 0], vr[rr + 0], a0);
                a1 = fmaf(wr[rr + 1], vr[rr + 1], a1);
                a2 = fmaf(wr[rr + 2], vr[rr + 2], a2);
                a3 = fmaf(wr[rr + 3], vr[rr + 3], a3);
            }
            g_K[i * 128 + j] = (a0 + a1) + (a2 + a3);
        }
    }
    __syncthreads();

    // ---- kfft: H = rfft(K, 32768) / MF (smem reused as FFT buffer) ----
    {
        float2* s   = reinterpret_cast<float2*>(smc);
        float2* tC  = s + 17408;
        float2* tF  = tC + 128;
        float2* tCN = tF + 128;
        float2* tFN = tCN + 128;
        if (tid < 128) {
            tC[tid] = g_twC[tid]; tF[tid] = g_twF[tid];
            tCN[tid] = g_twCN[tid]; tFN[tid] = g_twFN[tid];
        }
        __syncthreads();
        fft_fwd(s, tC, tF, reinterpret_cast<const float2*>(g_K));

        const float sc = 1.0f / (float)MF;
        if (tid == 0) {
            float2 Z0 = s[PADI(0)];
            g_H[0]  = make_float2((Z0.x + Z0.y) * sc, 0.f);
            g_H[MF] = make_float2((Z0.x - Z0.y) * sc, 0.f);
        }
        for (int k = tid + 1; k <= HALF; k += T_FFT) {
            int rk = PADI(rev4_14(k));
            int rm = PADI(rev4_14(MF - k));
            float2 a  = s[rk];
            float2 bb = cconj(s[rm]);
            float2 E  = make_float2(0.5f * (a.x + bb.x), 0.5f * (a.y + bb.y));
            float2 Od = make_float2(0.5f * (a.x - bb.x), 0.5f * (a.y - bb.y));
            float2 wN = cmul(tCN[k >> 7], tFN[k & 127]);
            float2 g  = make_float2(wN.y, -wN.x);
            float2 gOd = cmul(g, Od);
            g_H[k]      = make_float2((E.x + gOd.x) * sc, (E.y + gOd.y) * sc);
            g_H[MF - k] = make_float2((E.x - gOd.x) * sc, -(E.y - gOd.y) * sc);
        }
    }
}

// ---------------- kernel 4: per-row FFT conv + D*u --------------------------
__global__ __launch_bounds__(T_FFT) void k_conv(const float* __restrict__ u,
                                                const float* __restrict__ Dp,
                                                float* __restrict__ out) {
    extern __shared__ float2 sh2[];
    float2* s   = sh2;
    float2* tC  = s + 17408;
    float2* tF  = tC + 128;
    float2* tCN = tF + 128;
    float2* tFN = tCN + 128;
    const int tid = threadIdx.x;
    const int b = blockIdx.x;
    if (tid < 128) {
        tC[tid] = g_twC[tid]; tF[tid] = g_twF[tid];
        tCN[tid] = g_twCN[tid]; tFN[tid] = g_twFN[tid];
    }
    __syncthreads();

    const float2* u2 = reinterpret_cast<const float2*>(u) + (size_t)b * HALF;
    fft_fwd(s, tC, tF, u2);

    if (tid == 0) {
        float2 Z0 = s[PADI(0)];
        float X0 = Z0.x + Z0.y;
        float XM = Z0.x - Z0.y;
        float Y0 = X0 * g_H[0].x;
        float YM = XM * g_H[MF].x;
        s[PADI(0)] = make_float2(0.5f * (Y0 + YM), 0.5f * (Y0 - YM));
    }
    for (int k = tid + 1; k <= HALF; k += T_FFT) {
        int rk = PADI(rev4_14(k));
        int rm = PADI(rev4_14(MF - k));
        float2 a  = s[rk];
        float2 bb = cconj(s[rm]);
        float2 E  = make_float2(0.5f * (a.x + bb.x), 0.5f * (a.y + bb.y));
        float2 Od = make_float2(0.5f * (a.x - bb.x), 0.5f * (a.y - bb.y));
        float2 wN = cmul(tCN[k >> 7], tFN[k & 127]);
        float2 g  = make_float2(wN.y, -wN.x);
        float2 gOd = cmul(g, Od);
        float2 Xk = make_float2(E.x + gOd.x, E.y + gOd.y);
        float2 Xm = make_float2(E.x - gOd.x, -(E.y - gOd.y));
        float2 Yk = cmul(Xk, g_H[k]);
        float2 Ym = cmul(Xm, g_H[MF - k]);
        float2 cYm = cconj(Ym);
        float2 Ep  = make_float2(0.5f * (Yk.x + cYm.x), 0.5f * (Yk.y + cYm.y));
        float2 Dd  = make_float2(0.5f * (Yk.x - cYm.x), 0.5f * (Yk.y - cYm.y));
        float2 t1 = cmul(cconj(g), Dd);
        float2 t2 = cmul(g, cconj(Dd));
        s[rk] = make_float2(Ep.x + t1.x, Ep.y + t1.y);
        s[rm] = make_float2(Ep.x - t2.x, -Ep.y - t2.y);
    }
    __syncthreads();

    const float Dv = Dp[0];
    float2* o2 = reinterpret_cast<float2*>(out) + (size_t)b * HALF;
    fft_inv(s, tC, tF, o2, u2, Dv);
}

// ---------------- launch ----------------------------------------------------
extern "C" void kernel_launch(void* const* d_in, const int* in_sizes, int n_in,
                              void* d_out, int out_size) {
    const float* u  = (const float*)d_in[0];
    const float* A  = (const float*)d_in[1];
    const float* B  = (const float*)d_in[2];
    const float* C  = (const float*)d_in[3];
    const float* D  = (const float*)d_in[4];
    const float* ls = (const float*)d_in[5];
    float* out = (float*)d_out;

    const int smemFFT = (17408 + 4 * 128) * (int)sizeof(float2);   // 143360
    const int smemPw  = 8192 * (int)sizeof(float);                 // 32768

    cudaFuncSetAttribute(k_prep2, cudaFuncAttributeMaxDynamicSharedMemorySize, smemFFT);
    cudaFuncSetAttribute(k_conv, cudaFuncAttributeMaxDynamicSharedMemorySize, smemFFT);

    void* barp = nullptr;
    cudaGetSymbolAddress(&barp, g_bar);
    cudaMemsetAsync(barp, 0, sizeof(unsigned));

    k_disc<<<1, 256>>>(A, ls);
    k_power<<<64, 64, smemPw>>>(A, B);
    k_prep2<<<1, 512, smemFFT>>>(C);
    k_conv<<<512, T_FFT, smemFFT>>>(u, D, out);
}